// round 1
// baseline (speedup 1.0000x reference)
#include <cuda_runtime.h>

#define NN 2048
#define IN_DIM 1024
#define MLPW 16
#define HIDD 256
#define L2DIM 64
#define NCLS 4

// ---------------- scratch (device globals; no allocation) ----------------
__device__ float g_A[(size_t)NN * NN];     // unnormalized A = adj*mask + I
__device__ float g_XW[(size_t)NN * HIDD];  // dc-scaled x@Wg1
__device__ float g_AXW[(size_t)NN * HIDD]; // normalized A @ XW
__device__ float g_HW[(size_t)NN * NCLS];  // dc-scaled hid@Wg2
__device__ float g_rowsum[NN];
__device__ float g_colsum[NN];
__device__ float g_dr[NN];
__device__ float g_dc[NN];

// ---------------- kernel 0: zero colsum (needed every graph replay) -------
__global__ void zero_colsum_kernel() {
    int i = blockIdx.x * 256 + threadIdx.x;
    if (i < NN) g_colsum[i] = 0.f;
}

// ---------------- kernel 1: edge MLP -> A, rowsum --------------------------
// one block per row i, 256 threads, 8 cols/thread
__global__ __launch_bounds__(256) void edge_kernel(
    const float* __restrict__ adj, const float* __restrict__ xdeg,
    const float* __restrict__ ydeg, const float* __restrict__ Wm1,
    const float* __restrict__ bm1, const float* __restrict__ Wm2,
    const float* __restrict__ bm2) {
    __shared__ float sW1[48], sb1[16], sW2[32], sb2[2];
    int tid = threadIdx.x;
    if (tid < 48) sW1[tid] = Wm1[tid];
    if (tid < 16) sb1[tid] = bm1[tid];
    if (tid < 32) sW2[tid] = Wm2[tid];
    if (tid < 2)  sb2[tid] = bm2[tid];
    __syncthreads();

    int i = blockIdx.x;
    const float* arow = adj  + (size_t)i * NN;
    const float* xrow = xdeg + (size_t)i * NN;
    const float* yrow = ydeg + (size_t)i * NN;
    float* Arow = g_A + (size_t)i * NN;

    float rsum = 0.f;
#pragma unroll
    for (int t = 0; t < NN / 256; t++) {
        int j = tid + t * 256;
        float a = arow[j], xd = xrow[j], yd = yrow[j];
        float l0 = sb2[0], l1 = sb2[1];
#pragma unroll
        for (int k = 0; k < MLPW; k++) {
            float h = fmaf(a, sW1[k], fmaf(xd, sW1[16 + k], fmaf(yd, sW1[32 + k], sb1[k])));
            h = fmaxf(h, 0.f);
            l0 = fmaf(h, sW2[2 * k], l0);
            l1 = fmaf(h, sW2[2 * k + 1], l1);
        }
        // softmax(...)[1] over 2 logits == sigmoid(l1-l0) == 0.5*tanh(0.5*(l1-l0))+0.5
        float d = 0.5f * (l1 - l0);
        float th;
        asm("tanh.approx.f32 %0, %1;" : "=f"(th) : "f"(d));
        float mask = fmaf(0.5f, th, 0.5f);
        float Av = a * mask + (j == i ? 1.f : 0.f);
        Arow[j] = Av;
        rsum += Av;
    }
    // block reduction of rsum
    for (int off = 16; off; off >>= 1) rsum += __shfl_down_sync(0xffffffffu, rsum, off);
    __shared__ float red[8];
    if ((tid & 31) == 0) red[tid >> 5] = rsum;
    __syncthreads();
    if (tid == 0) {
        float s = 0.f;
#pragma unroll
        for (int w = 0; w < 8; w++) s += red[w];
        g_rowsum[i] = s;
    }
}

// ---------------- kernel 2: colsum (tiled partial + atomic) ----------------
// grid (NN/256, 16): each block sums 128 rows for 256 columns
__global__ __launch_bounds__(256) void colsum_kernel() {
    int j = blockIdx.x * 256 + threadIdx.x;
    int r0 = blockIdx.y * (NN / 16);
    float s = 0.f;
#pragma unroll 4
    for (int i = r0; i < r0 + NN / 16; i++) s += g_A[(size_t)i * NN + j];
    atomicAdd(&g_colsum[j], s);
}

// ---------------- kernel 3: dr/dc -----------------------------------------
__global__ void deg_kernel() {
    int i = blockIdx.x * 256 + threadIdx.x;
    if (i < NN) {
        float rs = g_rowsum[i];
        float cs = g_colsum[i];
        g_dr[i] = rs > 0.f ? rsqrtf(rs) : 0.f;
        g_dc[i] = cs > 0.f ? rsqrtf(cs) : 0.f;
    }
}

// ---------------- generic 64x64x16 fp32 tiled GEMM body --------------------
// C[M x 256] = rowscale[m] * (A[M x Kd] @ B[Kd x 256]); 256 threads, 4x4/thread
__device__ __forceinline__ void gemm_body(const float* __restrict__ A,
                                          const float* __restrict__ B,
                                          float* __restrict__ C, int Kd,
                                          const float* __restrict__ rowscale) {
    const int BM = 64, BN = 64, BK = 16;
    __shared__ float As[BK][BM];
    __shared__ float Bs[BK][BN];
    int tid = threadIdx.x;
    int tx = tid & 15;        // 0..15 -> 4 cols each
    int ty = tid >> 4;        // 0..15 -> 4 rows each
    int bm0 = blockIdx.y * BM;
    int bn0 = blockIdx.x * BN;

    // A-load mapping: row = tid/4 (0..63), quad = tid%4 (4 floats)
    int ar = tid >> 2, aq = tid & 3;
    // B-load mapping: row = tid/16 (0..15), quad = tid%16 (4 floats)
    int br = tid >> 4, bq = tid & 15;

    float acc[4][4];
#pragma unroll
    for (int r = 0; r < 4; r++)
#pragma unroll
        for (int c = 0; c < 4; c++) acc[r][c] = 0.f;

    for (int k0 = 0; k0 < Kd; k0 += BK) {
        float4 av = *reinterpret_cast<const float4*>(&A[(size_t)(bm0 + ar) * Kd + k0 + aq * 4]);
        As[aq * 4 + 0][ar] = av.x;
        As[aq * 4 + 1][ar] = av.y;
        As[aq * 4 + 2][ar] = av.z;
        As[aq * 4 + 3][ar] = av.w;
        *reinterpret_cast<float4*>(&Bs[br][bq * 4]) =
            *reinterpret_cast<const float4*>(&B[(size_t)(k0 + br) * HIDD + bn0 + bq * 4]);
        __syncthreads();
#pragma unroll
        for (int kk = 0; kk < BK; kk++) {
            float4 a4 = *reinterpret_cast<const float4*>(&As[kk][ty * 4]);
            float4 b4 = *reinterpret_cast<const float4*>(&Bs[kk][tx * 4]);
            float a[4] = {a4.x, a4.y, a4.z, a4.w};
            float b[4] = {b4.x, b4.y, b4.z, b4.w};
#pragma unroll
            for (int r = 0; r < 4; r++)
#pragma unroll
                for (int c = 0; c < 4; c++) acc[r][c] = fmaf(a[r], b[c], acc[r][c]);
        }
        __syncthreads();
    }
#pragma unroll
    for (int r = 0; r < 4; r++) {
        int row = bm0 + ty * 4 + r;
        float sc = rowscale[row];
        float4 o;
        o.x = acc[r][0] * sc; o.y = acc[r][1] * sc;
        o.z = acc[r][2] * sc; o.w = acc[r][3] * sc;
        *reinterpret_cast<float4*>(&C[(size_t)row * HIDD + bn0 + tx * 4]) = o;
    }
}

// GEMM1: g_XW = dc-scaled x @ Wg1   (K = 1024)
__global__ __launch_bounds__(256) void gemm1_kernel(const float* __restrict__ x,
                                                    const float* __restrict__ Wg1) {
    gemm_body(x, Wg1, g_XW, IN_DIM, g_dc);
}
// GEMM2: g_AXW = dr-scaled g_A @ g_XW   (K = 2048)
__global__ __launch_bounds__(256) void gemm2_kernel() {
    gemm_body(g_A, g_XW, g_AXW, NN, g_dr);
}

// ---------------- kernel: hid = AXW @ Wl2 + bl2; HW = dc * hid @ Wg2 -------
// one block (64 threads) per row
__global__ __launch_bounds__(64) void hid_kernel(const float* __restrict__ Wl2,
                                                 const float* __restrict__ bl2,
                                                 const float* __restrict__ Wg2,
                                                 float* __restrict__ hid_out) {
    int i = blockIdx.x;
    int c = threadIdx.x;
    __shared__ float srow[HIDD];
    __shared__ float shid[L2DIM];
#pragma unroll
    for (int t = c; t < HIDD; t += 64) srow[t] = g_AXW[(size_t)i * HIDD + t];
    __syncthreads();
    float acc = bl2[c];
#pragma unroll 8
    for (int k = 0; k < HIDD; k++) acc = fmaf(srow[k], Wl2[k * L2DIM + c], acc);
    hid_out[(size_t)i * L2DIM + c] = acc;
    shid[c] = acc;
    __syncthreads();
    if (c < NCLS) {
        float s = 0.f;
#pragma unroll
        for (int k = 0; k < L2DIM; k++) s = fmaf(shid[k], Wg2[k * NCLS + c], s);
        g_HW[i * NCLS + c] = s * g_dc[i];
    }
}

// ---------------- kernel: out[i] = dr[i] * sum_j A[i,j] * HW[j] ------------
// one block (256 threads) per row, HW staged in shared (32KB)
__global__ __launch_bounds__(256) void out_kernel(float* __restrict__ out) {
    int i = blockIdx.x;
    int tid = threadIdx.x;
    __shared__ float4 sHW[NN];
    const float4* hw4 = reinterpret_cast<const float4*>(g_HW);
#pragma unroll
    for (int t = tid; t < NN; t += 256) sHW[t] = hw4[t];
    __syncthreads();
    const float* arow = g_A + (size_t)i * NN;
    float ax = 0.f, ay = 0.f, az = 0.f, aw = 0.f;
#pragma unroll
    for (int t = 0; t < NN / 256; t++) {
        int j = tid + t * 256;
        float a = arow[j];
        float4 h = sHW[j];
        ax = fmaf(a, h.x, ax);
        ay = fmaf(a, h.y, ay);
        az = fmaf(a, h.z, az);
        aw = fmaf(a, h.w, aw);
    }
    for (int off = 16; off; off >>= 1) {
        ax += __shfl_down_sync(0xffffffffu, ax, off);
        ay += __shfl_down_sync(0xffffffffu, ay, off);
        az += __shfl_down_sync(0xffffffffu, az, off);
        aw += __shfl_down_sync(0xffffffffu, aw, off);
    }
    __shared__ float red[8][4];
    if ((tid & 31) == 0) {
        int w = tid >> 5;
        red[w][0] = ax; red[w][1] = ay; red[w][2] = az; red[w][3] = aw;
    }
    __syncthreads();
    if (tid < 4) {
        float s = 0.f;
#pragma unroll
        for (int w = 0; w < 8; w++) s += red[w][tid];
        out[i * NCLS + tid] = g_dr[i] * s;
    }
}

// ---------------- launch --------------------------------------------------
extern "C" void kernel_launch(void* const* d_in, const int* in_sizes, int n_in,
                              void* d_out, int out_size) {
    const float* x    = (const float*)d_in[0];
    const float* adj  = (const float*)d_in[1];
    const float* xdeg = (const float*)d_in[2];
    const float* ydeg = (const float*)d_in[3];
    const float* Wm1  = (const float*)d_in[4];
    const float* bm1  = (const float*)d_in[5];
    const float* Wm2  = (const float*)d_in[6];
    const float* bm2  = (const float*)d_in[7];
    const float* Wg1  = (const float*)d_in[8];
    const float* Wl2  = (const float*)d_in[9];
    const float* bl2  = (const float*)d_in[10];
    const float* Wg2  = (const float*)d_in[11];

    float* out = (float*)d_out;               // [2048, 4]
    float* hid = out + (size_t)NN * NCLS;     // [2048, 64]

    zero_colsum_kernel<<<NN / 256, 256>>>();
    edge_kernel<<<NN, 256>>>(adj, xdeg, ydeg, Wm1, bm1, Wm2, bm2);
    colsum_kernel<<<dim3(NN / 256, 16), 256>>>();
    deg_kernel<<<NN / 256, 256>>>();
    gemm1_kernel<<<dim3(HIDD / 64, NN / 64), 256>>>(x, Wg1);
    gemm2_kernel<<<dim3(HIDD / 64, NN / 64), 256>>>();
    hid_kernel<<<NN, 64>>>(Wl2, bl2, Wg2, hid);
    out_kernel<<<NN, 256>>>(out);
}

// round 2
// speedup vs baseline: 1.3023x; 1.3023x over previous
#include <cuda_runtime.h>
#include <cstdint>

#define NN 2048
#define IN_DIM 1024
#define MLPW 16
#define HIDD 256
#define L2DIM 64
#define NCLS 4

// ---------------- scratch (device globals; no allocation) ----------------
__device__ float g_A[(size_t)NN * NN];     // unnormalized A = adj*mask + I
__device__ float g_XW[(size_t)NN * HIDD];  // dc-scaled x@Wg1
__device__ float g_AXW[(size_t)NN * HIDD]; // normalized A @ XW
__device__ float g_HW[(size_t)NN * NCLS];  // dc-scaled hid@Wg2
__device__ float g_rowsum[NN];
__device__ float g_colsum[NN];
__device__ float g_dr[NN];
__device__ float g_dc[NN];

// ---------------- kernel 0: zero colsum (needed every graph replay) -------
__global__ void zero_colsum_kernel() {
    int i = blockIdx.x * 256 + threadIdx.x;
    if (i < NN) g_colsum[i] = 0.f;
}

// ---------------- kernel 1: edge MLP -> A, rowsum --------------------------
__global__ __launch_bounds__(256) void edge_kernel(
    const float* __restrict__ adj, const float* __restrict__ xdeg,
    const float* __restrict__ ydeg, const float* __restrict__ Wm1,
    const float* __restrict__ bm1, const float* __restrict__ Wm2,
    const float* __restrict__ bm2) {
    __shared__ float sW1[48], sb1[16], sW2[32], sb2[2];
    int tid = threadIdx.x;
    if (tid < 48) sW1[tid] = Wm1[tid];
    if (tid < 16) sb1[tid] = bm1[tid];
    if (tid < 32) sW2[tid] = Wm2[tid];
    if (tid < 2)  sb2[tid] = bm2[tid];
    __syncthreads();

    int i = blockIdx.x;
    const float* arow = adj  + (size_t)i * NN;
    const float* xrow = xdeg + (size_t)i * NN;
    const float* yrow = ydeg + (size_t)i * NN;
    float* Arow = g_A + (size_t)i * NN;

    float rsum = 0.f;
#pragma unroll
    for (int t = 0; t < NN / 256; t++) {
        int j = tid + t * 256;
        float a = arow[j], xd = xrow[j], yd = yrow[j];
        float l0 = sb2[0], l1 = sb2[1];
#pragma unroll
        for (int k = 0; k < MLPW; k++) {
            float h = fmaf(a, sW1[k], fmaf(xd, sW1[16 + k], fmaf(yd, sW1[32 + k], sb1[k])));
            h = fmaxf(h, 0.f);
            l0 = fmaf(h, sW2[2 * k], l0);
            l1 = fmaf(h, sW2[2 * k + 1], l1);
        }
        float d = 0.5f * (l1 - l0);
        float th;
        asm("tanh.approx.f32 %0, %1;" : "=f"(th) : "f"(d));
        float mask = fmaf(0.5f, th, 0.5f);
        float Av = a * mask + (j == i ? 1.f : 0.f);
        Arow[j] = Av;
        rsum += Av;
    }
    for (int off = 16; off; off >>= 1) rsum += __shfl_down_sync(0xffffffffu, rsum, off);
    __shared__ float red[8];
    if ((tid & 31) == 0) red[tid >> 5] = rsum;
    __syncthreads();
    if (tid == 0) {
        float s = 0.f;
#pragma unroll
        for (int w = 0; w < 8; w++) s += red[w];
        g_rowsum[i] = s;
    }
}

// ---------------- kernel 2: colsum (tiled partial + atomic) ----------------
__global__ __launch_bounds__(256) void colsum_kernel() {
    int j = blockIdx.x * 256 + threadIdx.x;
    int r0 = blockIdx.y * (NN / 16);
    float s = 0.f;
#pragma unroll 4
    for (int i = r0; i < r0 + NN / 16; i++) s += g_A[(size_t)i * NN + j];
    atomicAdd(&g_colsum[j], s);
}

// ---------------- kernel 3: dr/dc -----------------------------------------
__global__ void deg_kernel() {
    int i = blockIdx.x * 256 + threadIdx.x;
    if (i < NN) {
        float rs = g_rowsum[i];
        float cs = g_colsum[i];
        g_dr[i] = rs > 0.f ? rsqrtf(rs) : 0.f;
        g_dc[i] = cs > 0.f ? rsqrtf(cs) : 0.f;
    }
}

// ---------------- tf32 tensor-core GEMM -----------------------------------
// C[M x 256] = rowscale[m] * (A[M x Kd] @ B[Kd x 256])
// BM=64, BN=64, BK=16; 128 threads = 4 warps in 2x2, each warp 32x32.
// mma.sync.aligned.m16n8k8.row.col.f32.tf32.tf32.f32
__device__ __forceinline__ uint32_t f2tf32(float f) {
    uint32_t u;
    asm("cvt.rna.tf32.f32 %0, %1;" : "=r"(u) : "f"(f));
    return u;
}

__device__ __forceinline__ void mma_tf32(float& c0, float& c1, float& c2, float& c3,
                                         uint32_t a0, uint32_t a1, uint32_t a2, uint32_t a3,
                                         uint32_t b0, uint32_t b1) {
    asm volatile(
        "mma.sync.aligned.m16n8k8.row.col.f32.tf32.tf32.f32 "
        "{%0,%1,%2,%3}, {%4,%5,%6,%7}, {%8,%9}, {%0,%1,%2,%3};"
        : "+f"(c0), "+f"(c1), "+f"(c2), "+f"(c3)
        : "r"(a0), "r"(a1), "r"(a2), "r"(a3), "r"(b0), "r"(b1));
}

#define BM 64
#define BN 64
#define BK 16
#define SA_LD 20   // pad: stride 20 -> conflict-free frag reads (20r+k mod 32 distinct)
#define SB_LD 72   // pad: stride 72 -> conflict-free frag reads (8k+n mod 32 distinct)

__device__ __forceinline__ void gemm_tf32_body(const float* __restrict__ A,
                                               const float* __restrict__ B,
                                               float* __restrict__ C, int Kd,
                                               const float* __restrict__ rowscale) {
    __shared__ uint32_t sA[BM][SA_LD];
    __shared__ uint32_t sB[BK][SB_LD];

    int tid = threadIdx.x;
    int lane = tid & 31;
    int warp = tid >> 5;
    int wm = warp >> 1;         // 0..1 -> warp row (32 rows)
    int wn = warp & 1;          // 0..1 -> warp col (32 cols)
    int gid = lane >> 2;        // 0..7
    int tig = lane & 3;         // 0..3

    int bm0 = blockIdx.y * BM;
    int bn0 = blockIdx.x * BN;

    // global load mappings
    int a_row0 = tid >> 2, a_q = tid & 3;         // + 32 rows second iter
    int b_row = tid >> 4, b_c4 = tid & 15;        // + 8 rows second iter

    float acc[2][4][4];
#pragma unroll
    for (int mt = 0; mt < 2; mt++)
#pragma unroll
        for (int nt = 0; nt < 4; nt++)
#pragma unroll
            for (int e = 0; e < 4; e++) acc[mt][nt][e] = 0.f;

    for (int k0 = 0; k0 < Kd; k0 += BK) {
        // load A tile 64x16
#pragma unroll
        for (int it = 0; it < 2; it++) {
            int r = a_row0 + it * 32;
            float4 v = *reinterpret_cast<const float4*>(&A[(size_t)(bm0 + r) * Kd + k0 + a_q * 4]);
            uint4 u;
            u.x = f2tf32(v.x); u.y = f2tf32(v.y); u.z = f2tf32(v.z); u.w = f2tf32(v.w);
            *reinterpret_cast<uint4*>(&sA[r][a_q * 4]) = u;
        }
        // load B tile 16x64
#pragma unroll
        for (int it = 0; it < 2; it++) {
            int r = b_row + it * 8;
            float4 v = *reinterpret_cast<const float4*>(&B[(size_t)(k0 + r) * HIDD + bn0 + b_c4 * 4]);
            uint4 u;
            u.x = f2tf32(v.x); u.y = f2tf32(v.y); u.z = f2tf32(v.z); u.w = f2tf32(v.w);
            *reinterpret_cast<uint4*>(&sB[r][b_c4 * 4]) = u;
        }
        __syncthreads();

#pragma unroll
        for (int kk = 0; kk < BK; kk += 8) {
            uint32_t af[2][4];
#pragma unroll
            for (int mt = 0; mt < 2; mt++) {
                int rb = wm * 32 + mt * 16;
                af[mt][0] = sA[rb + gid][kk + tig];
                af[mt][1] = sA[rb + gid + 8][kk + tig];
                af[mt][2] = sA[rb + gid][kk + tig + 4];
                af[mt][3] = sA[rb + gid + 8][kk + tig + 4];
            }
            uint32_t bf[4][2];
#pragma unroll
            for (int nt = 0; nt < 4; nt++) {
                int nb = wn * 32 + nt * 8;
                bf[nt][0] = sB[kk + tig][nb + gid];
                bf[nt][1] = sB[kk + tig + 4][nb + gid];
            }
#pragma unroll
            for (int mt = 0; mt < 2; mt++)
#pragma unroll
                for (int nt = 0; nt < 4; nt++)
                    mma_tf32(acc[mt][nt][0], acc[mt][nt][1], acc[mt][nt][2], acc[mt][nt][3],
                             af[mt][0], af[mt][1], af[mt][2], af[mt][3],
                             bf[nt][0], bf[nt][1]);
        }
        __syncthreads();
    }

    // epilogue
#pragma unroll
    for (int mt = 0; mt < 2; mt++) {
        int r0 = bm0 + wm * 32 + mt * 16 + gid;
        int r1 = r0 + 8;
        float s0 = rowscale[r0];
        float s1 = rowscale[r1];
#pragma unroll
        for (int nt = 0; nt < 4; nt++) {
            int col = bn0 + wn * 32 + nt * 8 + 2 * tig;
            float2 v0 = make_float2(acc[mt][nt][0] * s0, acc[mt][nt][1] * s0);
            float2 v1 = make_float2(acc[mt][nt][2] * s1, acc[mt][nt][3] * s1);
            *reinterpret_cast<float2*>(&C[(size_t)r0 * HIDD + col]) = v0;
            *reinterpret_cast<float2*>(&C[(size_t)r1 * HIDD + col]) = v1;
        }
    }
}

__global__ __launch_bounds__(128) void gemm1_kernel(const float* __restrict__ x,
                                                    const float* __restrict__ Wg1) {
    gemm_tf32_body(x, Wg1, g_XW, IN_DIM, g_dc);
}
__global__ __launch_bounds__(128) void gemm2_kernel() {
    gemm_tf32_body(g_A, g_XW, g_AXW, NN, g_dr);
}

// ---------------- kernel: hid = AXW @ Wl2 + bl2; HW = dc * hid @ Wg2 -------
__global__ __launch_bounds__(64) void hid_kernel(const float* __restrict__ Wl2,
                                                 const float* __restrict__ bl2,
                                                 const float* __restrict__ Wg2,
                                                 float* __restrict__ hid_out) {
    int i = blockIdx.x;
    int c = threadIdx.x;
    __shared__ float srow[HIDD];
    __shared__ float shid[L2DIM];
#pragma unroll
    for (int t = c; t < HIDD; t += 64) srow[t] = g_AXW[(size_t)i * HIDD + t];
    __syncthreads();
    float acc = bl2[c];
#pragma unroll 8
    for (int k = 0; k < HIDD; k++) acc = fmaf(srow[k], Wl2[k * L2DIM + c], acc);
    hid_out[(size_t)i * L2DIM + c] = acc;
    shid[c] = acc;
    __syncthreads();
    if (c < NCLS) {
        float s = 0.f;
#pragma unroll
        for (int k = 0; k < L2DIM; k++) s = fmaf(shid[k], Wg2[k * NCLS + c], s);
        g_HW[i * NCLS + c] = s * g_dc[i];
    }
}

// ---------------- kernel: out[i] = dr[i] * sum_j A[i,j] * HW[j] ------------
__global__ __launch_bounds__(256) void out_kernel(float* __restrict__ out) {
    int i = blockIdx.x;
    int tid = threadIdx.x;
    __shared__ float4 sHW[NN];
    const float4* hw4 = reinterpret_cast<const float4*>(g_HW);
#pragma unroll
    for (int t = tid; t < NN; t += 256) sHW[t] = hw4[t];
    __syncthreads();
    const float* arow = g_A + (size_t)i * NN;
    float ax = 0.f, ay = 0.f, az = 0.f, aw = 0.f;
#pragma unroll
    for (int t = 0; t < NN / 256; t++) {
        int j = tid + t * 256;
        float a = arow[j];
        float4 h = sHW[j];
        ax = fmaf(a, h.x, ax);
        ay = fmaf(a, h.y, ay);
        az = fmaf(a, h.z, az);
        aw = fmaf(a, h.w, aw);
    }
    for (int off = 16; off; off >>= 1) {
        ax += __shfl_down_sync(0xffffffffu, ax, off);
        ay += __shfl_down_sync(0xffffffffu, ay, off);
        az += __shfl_down_sync(0xffffffffu, az, off);
        aw += __shfl_down_sync(0xffffffffu, aw, off);
    }
    __shared__ float red[8][4];
    if ((tid & 31) == 0) {
        int w = tid >> 5;
        red[w][0] = ax; red[w][1] = ay; red[w][2] = az; red[w][3] = aw;
    }
    __syncthreads();
    if (tid < 4) {
        float s = 0.f;
#pragma unroll
        for (int w = 0; w < 8; w++) s += red[w][tid];
        out[i * NCLS + tid] = g_dr[i] * s;
    }
}

// ---------------- launch --------------------------------------------------
extern "C" void kernel_launch(void* const* d_in, const int* in_sizes, int n_in,
                              void* d_out, int out_size) {
    const float* x    = (const float*)d_in[0];
    const float* adj  = (const float*)d_in[1];
    const float* xdeg = (const float*)d_in[2];
    const float* ydeg = (const float*)d_in[3];
    const float* Wm1  = (const float*)d_in[4];
    const float* bm1  = (const float*)d_in[5];
    const float* Wm2  = (const float*)d_in[6];
    const float* bm2  = (const float*)d_in[7];
    const float* Wg1  = (const float*)d_in[8];
    const float* Wl2  = (const float*)d_in[9];
    const float* bl2  = (const float*)d_in[10];
    const float* Wg2  = (const float*)d_in[11];

    float* out = (float*)d_out;               // [2048, 4]
    float* hid = out + (size_t)NN * NCLS;     // [2048, 64]

    zero_colsum_kernel<<<NN / 256, 256>>>();
    edge_kernel<<<NN, 256>>>(adj, xdeg, ydeg, Wm1, bm1, Wm2, bm2);
    colsum_kernel<<<dim3(NN / 256, 16), 256>>>();
    deg_kernel<<<NN / 256, 256>>>();
    gemm1_kernel<<<dim3(HIDD / BN, NN / BM), 128>>>(x, Wg1);
    gemm2_kernel<<<dim3(HIDD / BN, NN / BM), 128>>>();
    hid_kernel<<<NN, 64>>>(Wl2, bl2, Wg2, hid);
    out_kernel<<<NN, 256>>>(out);
}

// round 3
// speedup vs baseline: 1.5324x; 1.1767x over previous
#include <cuda_runtime.h>
#include <cstdint>

#define NN 2048
#define IN_DIM 1024
#define MLPW 16
#define HIDD 256
#define L2DIM 64
#define NCLS 4

// ---------------- scratch (device globals; no allocation) ----------------
__device__ float g_A[(size_t)NN * NN];     // unnormalized A = adj*mask + I (tf32-rounded)
__device__ float g_XW[(size_t)NN * HIDD];  // dc-scaled x@Wg1 (tf32-rounded)
__device__ float g_AXW[(size_t)NN * HIDD]; // dr-scaled A @ XW (fp32)
__device__ float g_HW[(size_t)NN * NCLS];  // dc-scaled hid@Wg2
__device__ float g_rowsum[NN];
__device__ float g_colsum[NN];

__device__ __forceinline__ float rsqrt_pos(float v) {
    return v > 0.f ? rsqrtf(v) : 0.f;
}
__device__ __forceinline__ uint32_t f2tf32(float f) {
    uint32_t u;
    asm("cvt.rna.tf32.f32 %0, %1;" : "=r"(u) : "f"(f));
    return u;
}

// ---------------- kernel 1: edge MLP -> A (tf32-rounded), rowsum ----------
// one block per row i, 256 threads; also zeroes g_colsum[i] for the next kernel
__global__ __launch_bounds__(256) void edge_kernel(
    const float* __restrict__ adj, const float* __restrict__ xdeg,
    const float* __restrict__ ydeg, const float* __restrict__ Wm1,
    const float* __restrict__ bm1, const float* __restrict__ Wm2,
    const float* __restrict__ bm2) {
    __shared__ float sW1[48], sb1[16], sW2[32], sb2[2];
    int tid = threadIdx.x;
    if (tid < 48) sW1[tid] = Wm1[tid];
    if (tid < 16) sb1[tid] = bm1[tid];
    if (tid < 32) sW2[tid] = Wm2[tid];
    if (tid < 2)  sb2[tid] = bm2[tid];
    int i = blockIdx.x;
    if (tid == 0) g_colsum[i] = 0.f;   // colsum_kernel runs strictly after us
    __syncthreads();

    const float* arow = adj  + (size_t)i * NN;
    const float* xrow = xdeg + (size_t)i * NN;
    const float* yrow = ydeg + (size_t)i * NN;
    float* Arow = g_A + (size_t)i * NN;

    float rsum = 0.f;
#pragma unroll
    for (int t = 0; t < NN / 256; t++) {
        int j = tid + t * 256;
        float a = arow[j], xd = xrow[j], yd = yrow[j];
        float l0 = sb2[0], l1 = sb2[1];
#pragma unroll
        for (int k = 0; k < MLPW; k++) {
            float h = fmaf(a, sW1[k], fmaf(xd, sW1[16 + k], fmaf(yd, sW1[32 + k], sb1[k])));
            h = fmaxf(h, 0.f);
            l0 = fmaf(h, sW2[2 * k], l0);
            l1 = fmaf(h, sW2[2 * k + 1], l1);
        }
        float d = 0.5f * (l1 - l0);
        float th;
        asm("tanh.approx.f32 %0, %1;" : "=f"(th) : "f"(d));
        float mask = fmaf(0.5f, th, 0.5f);
        float Av = a * mask + (j == i ? 1.f : 0.f);
        Av = __uint_as_float(f2tf32(Av));   // pre-round for tensor-core consumption
        Arow[j] = Av;
        rsum += Av;
    }
    for (int off = 16; off; off >>= 1) rsum += __shfl_down_sync(0xffffffffu, rsum, off);
    __shared__ float red[8];
    if ((tid & 31) == 0) red[tid >> 5] = rsum;
    __syncthreads();
    if (tid == 0) {
        float s = 0.f;
#pragma unroll
        for (int w = 0; w < 8; w++) s += red[w];
        g_rowsum[i] = s;
    }
}

// ---------------- kernel 2: colsum (tiled partial + atomic) ----------------
__global__ __launch_bounds__(256) void colsum_kernel() {
    int j = blockIdx.x * 256 + threadIdx.x;
    int r0 = blockIdx.y * (NN / 16);
    float s = 0.f;
#pragma unroll 4
    for (int i = r0; i < r0 + NN / 16; i++) s += g_A[(size_t)i * NN + j];
    atomicAdd(&g_colsum[j], s);
}

// ---------------- tf32 tensor-core GEMM, 8 warps, double-buffered ---------
// C[M x 256] = rsqrt_pos(sumvec[m]) * (A[M x Kd] @ B[Kd x 256])
// BM=64 BN=64 BK=16, 256 threads; warp (wm 0..3, wn 0..1) owns 16x32.
__device__ __forceinline__ void mma_tf32(float& c0, float& c1, float& c2, float& c3,
                                         uint32_t a0, uint32_t a1, uint32_t a2, uint32_t a3,
                                         uint32_t b0, uint32_t b1) {
    asm volatile(
        "mma.sync.aligned.m16n8k8.row.col.f32.tf32.tf32.f32 "
        "{%0,%1,%2,%3}, {%4,%5,%6,%7}, {%8,%9}, {%0,%1,%2,%3};"
        : "+f"(c0), "+f"(c1), "+f"(c2), "+f"(c3)
        : "r"(a0), "r"(a1), "r"(a2), "r"(a3), "r"(b0), "r"(b1));
}

#define BM 64
#define BN 64
#define BK 16
#define SA_LD 20   // pad: 20r+k distinct mod 32 over the frag footprint
#define SB_LD 72   // pad: 72k+n distinct mod 32 over the frag footprint

template <bool CONVERT, bool TF32OUT>
__device__ __forceinline__ void gemm_tf32_body(const float* __restrict__ A,
                                               const float* __restrict__ B,
                                               float* __restrict__ C, int Kd,
                                               const float* __restrict__ sumvec) {
    __shared__ uint32_t sA[2][BM][SA_LD];
    __shared__ uint32_t sB[2][BK][SB_LD];

    int tid = threadIdx.x;
    int lane = tid & 31;
    int warp = tid >> 5;
    int wm = warp & 3;          // row base wm*16
    int wn = warp >> 2;         // col base wn*32
    int gid = lane >> 2;
    int tig = lane & 3;

    int bm0 = blockIdx.y * BM;
    int bn0 = blockIdx.x * BN;

    int a_row = tid >> 2, a_q = tid & 3;   // A: 64 rows x 4 float4
    int b_row = tid >> 4, b_c4 = tid & 15; // B: 16 rows x 16 float4

    const float* Aptr = A + (size_t)(bm0 + a_row) * Kd + a_q * 4;
    const float* Bptr = B + (size_t)b_row * HIDD + bn0 + b_c4 * 4;

    float acc[4][4];
#pragma unroll
    for (int nt = 0; nt < 4; nt++)
#pragma unroll
        for (int e = 0; e < 4; e++) acc[nt][e] = 0.f;

    int niter = Kd / BK;

    auto sts_tile = [&](int s, float4 av, float4 bv) {
        uint4 ua, ub;
        if (CONVERT) {
            ua.x = f2tf32(av.x); ua.y = f2tf32(av.y); ua.z = f2tf32(av.z); ua.w = f2tf32(av.w);
            ub.x = f2tf32(bv.x); ub.y = f2tf32(bv.y); ub.z = f2tf32(bv.z); ub.w = f2tf32(bv.w);
        } else {
            ua = *reinterpret_cast<uint4*>(&av);
            ub = *reinterpret_cast<uint4*>(&bv);
        }
        *reinterpret_cast<uint4*>(&sA[s][a_row][a_q * 4]) = ua;
        *reinterpret_cast<uint4*>(&sB[s][b_row][b_c4 * 4]) = ub;
    };

    // prologue: tile0 -> stage0; tile1 -> regs
    float4 av = *reinterpret_cast<const float4*>(Aptr);
    float4 bv = *reinterpret_cast<const float4*>(Bptr);
    sts_tile(0, av, bv);
    av = *reinterpret_cast<const float4*>(Aptr + BK);
    bv = *reinterpret_cast<const float4*>(Bptr + (size_t)BK * HIDD);
    __syncthreads();

    for (int i = 0; i < niter; i++) {
        int s = i & 1;
        float4 nav, nbv;
        if (i + 2 < niter) {   // prefetch tile i+2 (overlaps compute below)
            nav = *reinterpret_cast<const float4*>(Aptr + (size_t)(i + 2) * BK);
            nbv = *reinterpret_cast<const float4*>(Bptr + (size_t)(i + 2) * BK * HIDD);
        }
        // compute stage s
#pragma unroll
        for (int kk = 0; kk < BK; kk += 8) {
            int r0 = wm * 16 + gid;
            uint32_t a0 = sA[s][r0][kk + tig];
            uint32_t a1 = sA[s][r0 + 8][kk + tig];
            uint32_t a2 = sA[s][r0][kk + tig + 4];
            uint32_t a3 = sA[s][r0 + 8][kk + tig + 4];
#pragma unroll
            for (int nt = 0; nt < 4; nt++) {
                int nb = wn * 32 + nt * 8 + gid;
                uint32_t b0 = sB[s][kk + tig][nb];
                uint32_t b1 = sB[s][kk + tig + 4][nb];
                mma_tf32(acc[nt][0], acc[nt][1], acc[nt][2], acc[nt][3],
                         a0, a1, a2, a3, b0, b1);
            }
        }
        if (i + 1 < niter) {
            sts_tile(s ^ 1, av, bv);   // stage s^1 was last read in iter i-1 (sealed by its sync)
            av = nav; bv = nbv;
        }
        __syncthreads();
    }

    // epilogue: rowscale = rsqrt_pos(sumvec[row])
    int r0 = bm0 + wm * 16 + gid;
    int r1 = r0 + 8;
    float s0 = rsqrt_pos(sumvec[r0]);
    float s1 = rsqrt_pos(sumvec[r1]);
#pragma unroll
    for (int nt = 0; nt < 4; nt++) {
        int col = bn0 + wn * 32 + nt * 8 + 2 * tig;
        float v00 = acc[nt][0] * s0, v01 = acc[nt][1] * s0;
        float v10 = acc[nt][2] * s1, v11 = acc[nt][3] * s1;
        if (TF32OUT) {
            v00 = __uint_as_float(f2tf32(v00)); v01 = __uint_as_float(f2tf32(v01));
            v10 = __uint_as_float(f2tf32(v10)); v11 = __uint_as_float(f2tf32(v11));
        }
        *reinterpret_cast<float2*>(&C[(size_t)r0 * HIDD + col]) = make_float2(v00, v01);
        *reinterpret_cast<float2*>(&C[(size_t)r1 * HIDD + col]) = make_float2(v10, v11);
    }
}

// GEMM1: g_XW = dc * (x @ Wg1), tf32-rounded output for gemm2
__global__ __launch_bounds__(256) void gemm1_kernel(const float* __restrict__ x,
                                                    const float* __restrict__ Wg1) {
    gemm_tf32_body<true, true>(x, Wg1, g_XW, IN_DIM, g_colsum);
}
// GEMM2: g_AXW = dr * (g_A @ g_XW), fp32 output (A, XW already tf32)
__global__ __launch_bounds__(256) void gemm2_kernel() {
    gemm_tf32_body<false, false>(g_A, g_XW, g_AXW, NN, g_rowsum);
}

// ---------------- hid = AXW @ Wl2 + bl2;  HW = dc * (hid @ Wg2) ------------
// 128 blocks x 256 threads, 16 rows per block
__global__ __launch_bounds__(256) void hid_kernel(const float* __restrict__ Wl2,
                                                  const float* __restrict__ bl2,
                                                  const float* __restrict__ Wg2,
                                                  float* __restrict__ hid_out) {
    __shared__ float sAXW[16][HIDD];
    __shared__ float sHid[16][L2DIM + 1];
    int tid = threadIdx.x;
    int rowbase = blockIdx.x * 16;

#pragma unroll
    for (int t = 0; t < 16; t++) {
        int idx = tid + t * 256;
        sAXW[idx >> 8][idx & 255] = g_AXW[(size_t)rowbase * HIDD + idx];
    }
    __syncthreads();

    int c = tid & 63;
    int rq = tid >> 6;   // 0..3
    float acc[4];
    float b = bl2[c];
#pragma unroll
    for (int it = 0; it < 4; it++) acc[it] = b;
#pragma unroll 4
    for (int k = 0; k < HIDD; k++) {
        float w = __ldg(&Wl2[k * L2DIM + c]);
#pragma unroll
        for (int it = 0; it < 4; it++)
            acc[it] = fmaf(sAXW[it * 4 + rq][k], w, acc[it]);
    }
#pragma unroll
    for (int it = 0; it < 4; it++) {
        int row = it * 4 + rq;
        hid_out[(size_t)(rowbase + row) * L2DIM + c] = acc[it];
        sHid[row][c] = acc[it];
    }
    __syncthreads();
    if (tid < 64) {
        int r = tid >> 2, cls = tid & 3;
        float s = 0.f;
#pragma unroll
        for (int k = 0; k < L2DIM; k++) s = fmaf(sHid[r][k], Wg2[k * NCLS + cls], s);
        g_HW[(size_t)(rowbase + r) * NCLS + cls] = s * rsqrt_pos(g_colsum[rowbase + r]);
    }
}

// ---------------- out[i] = dr[i] * sum_j A[i,j] * HW[j] --------------------
// 256 blocks x 256 threads, 8 rows per block; HW staged once per block
__global__ __launch_bounds__(256) void out_kernel(float* __restrict__ out) {
    int tid = threadIdx.x;
    __shared__ float4 sHW[NN];
    const float4* hw4 = reinterpret_cast<const float4*>(g_HW);
#pragma unroll
    for (int t = 0; t < NN / 256; t++) sHW[tid + t * 256] = hw4[tid + t * 256];
    __syncthreads();

    __shared__ float red[8][4];
    for (int r = 0; r < 8; r++) {
        int i = blockIdx.x * 8 + r;
        const float* arow = g_A + (size_t)i * NN;
        float ax = 0.f, ay = 0.f, az = 0.f, aw = 0.f;
#pragma unroll
        for (int t = 0; t < NN / 256; t++) {
            int j = tid + t * 256;
            float a = arow[j];
            float4 h = sHW[j];
            ax = fmaf(a, h.x, ax);
            ay = fmaf(a, h.y, ay);
            az = fmaf(a, h.z, az);
            aw = fmaf(a, h.w, aw);
        }
        for (int off = 16; off; off >>= 1) {
            ax += __shfl_down_sync(0xffffffffu, ax, off);
            ay += __shfl_down_sync(0xffffffffu, ay, off);
            az += __shfl_down_sync(0xffffffffu, az, off);
            aw += __shfl_down_sync(0xffffffffu, aw, off);
        }
        if ((tid & 31) == 0) {
            int w = tid >> 5;
            red[w][0] = ax; red[w][1] = ay; red[w][2] = az; red[w][3] = aw;
        }
        __syncthreads();
        if (tid < 4) {
            float s = 0.f;
#pragma unroll
            for (int w = 0; w < 8; w++) s += red[w][tid];
            out[i * NCLS + tid] = rsqrt_pos(g_rowsum[i]) * s;
        }
        __syncthreads();
    }
}

// ---------------- launch --------------------------------------------------
extern "C" void kernel_launch(void* const* d_in, const int* in_sizes, int n_in,
                              void* d_out, int out_size) {
    const float* x    = (const float*)d_in[0];
    const float* adj  = (const float*)d_in[1];
    const float* xdeg = (const float*)d_in[2];
    const float* ydeg = (const float*)d_in[3];
    const float* Wm1  = (const float*)d_in[4];
    const float* bm1  = (const float*)d_in[5];
    const float* Wm2  = (const float*)d_in[6];
    const float* bm2  = (const float*)d_in[7];
    const float* Wg1  = (const float*)d_in[8];
    const float* Wl2  = (const float*)d_in[9];
    const float* bl2  = (const float*)d_in[10];
    const float* Wg2  = (const float*)d_in[11];

    float* out = (float*)d_out;               // [2048, 4]
    float* hid = out + (size_t)NN * NCLS;     // [2048, 64]

    edge_kernel<<<NN, 256>>>(adj, xdeg, ydeg, Wm1, bm1, Wm2, bm2);
    colsum_kernel<<<dim3(NN / 256, 16), 256>>>();
    gemm1_kernel<<<dim3(HIDD / BN, NN / BM), 256>>>(x, Wg1);
    gemm2_kernel<<<dim3(HIDD / BN, NN / BM), 256>>>();
    hid_kernel<<<NN / 16, 256>>>(Wl2, bl2, Wg2, hid);
    out_kernel<<<NN / 8, 256>>>(out);
}

// round 4
// speedup vs baseline: 1.9997x; 1.3050x over previous
#include <cuda_runtime.h>
#include <cstdint>

#define NN 2048
#define IN_DIM 1024
#define MLPW 16
#define HIDD 256
#define L2DIM 64
#define NCLS 4

// ---------------- scratch (device globals; no allocation) ----------------
__device__ float g_A[(size_t)NN * NN];       // unnormalized A = adj*mask + I (tf32-rounded)
__device__ float g_Xt[(size_t)NN * IN_DIM];  // tf32-rounded x
__device__ float g_Wt[(size_t)IN_DIM * HIDD];// tf32-rounded Wg1
__device__ float g_XW[(size_t)NN * HIDD];    // dc-scaled x@Wg1 (tf32-rounded)
__device__ float g_AXW[(size_t)NN * HIDD];   // dr-scaled A @ XW (fp32)
__device__ float g_HW[(size_t)NN * NCLS];    // dc-scaled hid@Wg2
__device__ float g_rowsum[NN];
__device__ float g_colsum[NN];

__device__ __forceinline__ float rsqrt_pos(float v) {
    return v > 0.f ? rsqrtf(v) : 0.f;
}
__device__ __forceinline__ uint32_t f2tf32(float f) {
    uint32_t u;
    asm("cvt.rna.tf32.f32 %0, %1;" : "=r"(u) : "f"(f));
    return u;
}

// ---------------- cp.async helpers ----------------------------------------
__device__ __forceinline__ void cp_async16(uint32_t smem, const void* gptr) {
    asm volatile("cp.async.cg.shared.global [%0], [%1], 16;\n" ::"r"(smem), "l"(gptr));
}
__device__ __forceinline__ void cp_commit() {
    asm volatile("cp.async.commit_group;\n");
}
template <int N>
__device__ __forceinline__ void cp_wait() {
    asm volatile("cp.async.wait_group %0;\n" ::"n"(N));
}

// ---------------- kernel 1: edge MLP -> A (tf32-rounded), rowsum ----------
__global__ __launch_bounds__(256) void edge_kernel(
    const float* __restrict__ adj, const float* __restrict__ xdeg,
    const float* __restrict__ ydeg, const float* __restrict__ Wm1,
    const float* __restrict__ bm1, const float* __restrict__ Wm2,
    const float* __restrict__ bm2) {
    __shared__ float sW1[48], sb1[16], sW2[32], sb2[2];
    int tid = threadIdx.x;
    if (tid < 48) sW1[tid] = Wm1[tid];
    if (tid < 16) sb1[tid] = bm1[tid];
    if (tid < 32) sW2[tid] = Wm2[tid];
    if (tid < 2)  sb2[tid] = bm2[tid];
    int i = blockIdx.x;
    if (tid == 0) g_colsum[i] = 0.f;   // prep_kernel's colsum runs strictly after
    __syncthreads();

    const float* arow = adj  + (size_t)i * NN;
    const float* xrow = xdeg + (size_t)i * NN;
    const float* yrow = ydeg + (size_t)i * NN;
    float* Arow = g_A + (size_t)i * NN;

    float rsum = 0.f;
#pragma unroll
    for (int t = 0; t < NN / 256; t++) {
        int j = tid + t * 256;
        float a = arow[j], xd = xrow[j], yd = yrow[j];
        float l0 = sb2[0], l1 = sb2[1];
#pragma unroll
        for (int k = 0; k < MLPW; k++) {
            float h = fmaf(a, sW1[k], fmaf(xd, sW1[16 + k], fmaf(yd, sW1[32 + k], sb1[k])));
            h = fmaxf(h, 0.f);
            l0 = fmaf(h, sW2[2 * k], l0);
            l1 = fmaf(h, sW2[2 * k + 1], l1);
        }
        float d = 0.5f * (l1 - l0);
        float th;
        asm("tanh.approx.f32 %0, %1;" : "=f"(th) : "f"(d));
        float mask = fmaf(0.5f, th, 0.5f);
        float Av = a * mask + (j == i ? 1.f : 0.f);
        Av = __uint_as_float(f2tf32(Av));
        Arow[j] = Av;
        rsum += Av;
    }
    for (int off = 16; off; off >>= 1) rsum += __shfl_down_sync(0xffffffffu, rsum, off);
    __shared__ float red[8];
    if ((tid & 31) == 0) red[tid >> 5] = rsum;
    __syncthreads();
    if (tid == 0) {
        float s = 0.f;
#pragma unroll
        for (int w = 0; w < 8; w++) s += red[w];
        g_rowsum[i] = s;
    }
}

// ---------------- kernel 2: prep = colsum + tf32-round x, Wg1 --------------
// blocks 0..127: colsum partials; 128..639: round x; 640..703: round Wg1
__global__ __launch_bounds__(256) void prep_kernel(const float* __restrict__ x,
                                                   const float* __restrict__ Wg1) {
    int b = blockIdx.x, tid = threadIdx.x;
    if (b < 128) {
        int j = (b & 7) * 256 + tid;
        int r0 = (b >> 3) * (NN / 16);
        float s = 0.f;
#pragma unroll 4
        for (int i = r0; i < r0 + NN / 16; i++) s += g_A[(size_t)i * NN + j];
        atomicAdd(&g_colsum[j], s);
    } else if (b < 640) {
        size_t idx4 = (size_t)(b - 128) * 1024 + tid;
        const float4* src = reinterpret_cast<const float4*>(x);
        float4* dst = reinterpret_cast<float4*>(g_Xt);
#pragma unroll
        for (int t = 0; t < 4; t++) {
            float4 v = src[idx4 + t * 256];
            uint4 u;
            u.x = f2tf32(v.x); u.y = f2tf32(v.y); u.z = f2tf32(v.z); u.w = f2tf32(v.w);
            dst[idx4 + t * 256] = *reinterpret_cast<float4*>(&u);
        }
    } else {
        size_t idx4 = (size_t)(b - 640) * 1024 + tid;
        const float4* src = reinterpret_cast<const float4*>(Wg1);
        float4* dst = reinterpret_cast<float4*>(g_Wt);
#pragma unroll
        for (int t = 0; t < 4; t++) {
            float4 v = src[idx4 + t * 256];
            uint4 u;
            u.x = f2tf32(v.x); u.y = f2tf32(v.y); u.z = f2tf32(v.z); u.w = f2tf32(v.w);
            dst[idx4 + t * 256] = *reinterpret_cast<float4*>(&u);
        }
    }
}

// ---------------- tf32 tensor-core GEMM, cp.async 3-stage ------------------
// C[M x 256] = rsqrt_pos(sumvec[m]) * (A[M x Kd] @ B[Kd x 256])
// BM=64 BN=64 BK=32, 256 threads (8 warps, warp = 16x32 tile).
// smem XOR quad-swizzle: A q' = q ^ (row&7); B q' = q ^ ((row&3)<<1).
__device__ __forceinline__ void mma_tf32(float& c0, float& c1, float& c2, float& c3,
                                         uint32_t a0, uint32_t a1, uint32_t a2, uint32_t a3,
                                         uint32_t b0, uint32_t b1) {
    asm volatile(
        "mma.sync.aligned.m16n8k8.row.col.f32.tf32.tf32.f32 "
        "{%0,%1,%2,%3}, {%4,%5,%6,%7}, {%8,%9}, {%0,%1,%2,%3};"
        : "+f"(c0), "+f"(c1), "+f"(c2), "+f"(c3)
        : "r"(a0), "r"(a1), "r"(a2), "r"(a3), "r"(b0), "r"(b1));
}

#define BM 64
#define BN 64
#define BKK 32
#define NSTG 3

template <bool TF32OUT>
__device__ __forceinline__ void gemm_body(const float* __restrict__ A,
                                          const float* __restrict__ B,
                                          float* __restrict__ C, int Kd,
                                          const float* __restrict__ sumvec) {
    __shared__ uint32_t sA[NSTG][BM][BKK];   // 24KB
    __shared__ uint32_t sB[NSTG][BKK][BN];   // 24KB

    const int tid = threadIdx.x;
    const int lane = tid & 31, warp = tid >> 5;
    const int wm = warp & 3, wn = warp >> 2;
    const int gid = lane >> 2, tig = lane & 3;
    const int bm0 = blockIdx.y * BM, bn0 = blockIdx.x * BN;

    // cp.async mappings: A 64 rows x 8 quads (x2), B 32 rows x 16 quads (x2)
    const int a_row = tid >> 3, a_q = tid & 7;
    const int b_row = tid >> 4, b_c4 = tid & 15;
    const int aq = (a_q ^ (a_row & 7)) << 2;          // (a_row+32)&7 == a_row&7
    const int bq = (b_c4 ^ ((b_row & 3) << 1)) << 2;  // (b_row+16)&3 == b_row&3

    const float* Ap0 = A + (size_t)(bm0 + a_row) * Kd + a_q * 4;
    const float* Ap1 = Ap0 + (size_t)32 * Kd;
    const float* Bp0 = B + (size_t)b_row * HIDD + bn0 + b_c4 * 4;
    const float* Bp1 = Bp0 + (size_t)16 * HIDD;

    uint32_t dA0[NSTG], dA1[NSTG], dB0[NSTG], dB1[NSTG];
#pragma unroll
    for (int s = 0; s < NSTG; s++) {
        dA0[s] = (uint32_t)__cvta_generic_to_shared(&sA[s][a_row][aq]);
        dA1[s] = (uint32_t)__cvta_generic_to_shared(&sA[s][a_row + 32][aq]);
        dB0[s] = (uint32_t)__cvta_generic_to_shared(&sB[s][b_row][bq]);
        dB1[s] = (uint32_t)__cvta_generic_to_shared(&sB[s][b_row + 16][bq]);
    }

    const int niter = Kd / BKK;

    auto issue = [&](int kt, int s) {
        cp_async16(dA0[s], Ap0 + (size_t)kt * BKK);
        cp_async16(dA1[s], Ap1 + (size_t)kt * BKK);
        cp_async16(dB0[s], Bp0 + (size_t)kt * BKK * HIDD);
        cp_async16(dB1[s], Bp1 + (size_t)kt * BKK * HIDD);
    };

    for (int p = 0; p < NSTG - 1; p++) { issue(p, p); cp_commit(); }

    float acc[4][4] = {};
    const int r0 = wm * 16 + gid, r1 = r0 + 8;  // r0&7 == r1&7 == gid

    for (int i = 0; i < niter; i++) {
        cp_wait<NSTG - 2>();
        __syncthreads();
        if (i + NSTG - 1 < niter) issue(i + NSTG - 1, (i + NSTG - 1) % NSTG);
        cp_commit();
        const int s = i % NSTG;
#pragma unroll
        for (int kk = 0; kk < BKK; kk += 8) {
            const int qa = kk >> 2;
            uint32_t a0 = sA[s][r0][((qa ^ gid) << 2) + tig];
            uint32_t a1 = sA[s][r1][((qa ^ gid) << 2) + tig];
            uint32_t a2 = sA[s][r0][(((qa + 1) ^ gid) << 2) + tig];
            uint32_t a3 = sA[s][r1][(((qa + 1) ^ gid) << 2) + tig];
            const int rb0 = kk + tig, rb1 = kk + tig + 4;
            const int t2 = tig << 1;
#pragma unroll
            for (int nt = 0; nt < 4; nt++) {
                int q = wn * 8 + nt * 2 + (gid >> 2);
                int col = ((q ^ t2) << 2) + (gid & 3);
                uint32_t b0 = sB[s][rb0][col];
                uint32_t b1 = sB[s][rb1][col];
                mma_tf32(acc[nt][0], acc[nt][1], acc[nt][2], acc[nt][3],
                         a0, a1, a2, a3, b0, b1);
            }
        }
    }

    // epilogue: rowscale = rsqrt_pos(sumvec[row])
    const int gr0 = bm0 + r0, gr1 = bm0 + r1;
    float s0 = rsqrt_pos(sumvec[gr0]);
    float s1 = rsqrt_pos(sumvec[gr1]);
#pragma unroll
    for (int nt = 0; nt < 4; nt++) {
        int col = bn0 + wn * 32 + nt * 8 + 2 * tig;
        float v00 = acc[nt][0] * s0, v01 = acc[nt][1] * s0;
        float v10 = acc[nt][2] * s1, v11 = acc[nt][3] * s1;
        if (TF32OUT) {
            v00 = __uint_as_float(f2tf32(v00)); v01 = __uint_as_float(f2tf32(v01));
            v10 = __uint_as_float(f2tf32(v10)); v11 = __uint_as_float(f2tf32(v11));
        }
        *reinterpret_cast<float2*>(&C[(size_t)gr0 * HIDD + col]) = make_float2(v00, v01);
        *reinterpret_cast<float2*>(&C[(size_t)gr1 * HIDD + col]) = make_float2(v10, v11);
    }
}

// GEMM1: g_XW = dc * (g_Xt @ g_Wt), tf32-rounded output for gemm2
__global__ __launch_bounds__(256) void gemm1_kernel() {
    gemm_body<true>(g_Xt, g_Wt, g_XW, IN_DIM, g_colsum);
}
// GEMM2: g_AXW = dr * (g_A @ g_XW), fp32 output
__global__ __launch_bounds__(256) void gemm2_kernel() {
    gemm_body<false>(g_A, g_XW, g_AXW, NN, g_rowsum);
}

// ---------------- hid = AXW @ Wl2 + bl2;  HW = dc * (hid @ Wg2) ------------
__global__ __launch_bounds__(256) void hid_kernel(const float* __restrict__ Wl2,
                                                  const float* __restrict__ bl2,
                                                  const float* __restrict__ Wg2,
                                                  float* __restrict__ hid_out) {
    __shared__ float sAXW[16][HIDD];
    __shared__ float sHid[16][L2DIM + 1];
    int tid = threadIdx.x;
    int rowbase = blockIdx.x * 16;

#pragma unroll
    for (int t = 0; t < 16; t++) {
        int idx = tid + t * 256;
        sAXW[idx >> 8][idx & 255] = g_AXW[(size_t)rowbase * HIDD + idx];
    }
    __syncthreads();

    int c = tid & 63;
    int rq = tid >> 6;
    float acc[4];
    float b = bl2[c];
#pragma unroll
    for (int it = 0; it < 4; it++) acc[it] = b;
#pragma unroll 4
    for (int k = 0; k < HIDD; k++) {
        float w = __ldg(&Wl2[k * L2DIM + c]);
#pragma unroll
        for (int it = 0; it < 4; it++)
            acc[it] = fmaf(sAXW[it * 4 + rq][k], w, acc[it]);
    }
#pragma unroll
    for (int it = 0; it < 4; it++) {
        int row = it * 4 + rq;
        hid_out[(size_t)(rowbase + row) * L2DIM + c] = acc[it];
        sHid[row][c] = acc[it];
    }
    __syncthreads();
    if (tid < 64) {
        int r = tid >> 2, cls = tid & 3;
        float s = 0.f;
#pragma unroll
        for (int k = 0; k < L2DIM; k++) s = fmaf(sHid[r][k], Wg2[k * NCLS + cls], s);
        g_HW[(size_t)(rowbase + r) * NCLS + cls] = s * rsqrt_pos(g_colsum[rowbase + r]);
    }
}

// ---------------- out[i] = dr[i] * sum_j A[i,j] * HW[j] --------------------
__global__ __launch_bounds__(256) void out_kernel(float* __restrict__ out) {
    int tid = threadIdx.x;
    __shared__ float4 sHW[NN];
    const float4* hw4 = reinterpret_cast<const float4*>(g_HW);
#pragma unroll
    for (int t = 0; t < NN / 256; t++) sHW[tid + t * 256] = hw4[tid + t * 256];
    __syncthreads();

    __shared__ float red[8][4];
    for (int r = 0; r < 8; r++) {
        int i = blockIdx.x * 8 + r;
        const float* arow = g_A + (size_t)i * NN;
        float ax = 0.f, ay = 0.f, az = 0.f, aw = 0.f;
#pragma unroll
        for (int t = 0; t < NN / 256; t++) {
            int j = tid + t * 256;
            float a = arow[j];
            float4 h = sHW[j];
            ax = fmaf(a, h.x, ax);
            ay = fmaf(a, h.y, ay);
            az = fmaf(a, h.z, az);
            aw = fmaf(a, h.w, aw);
        }
        for (int off = 16; off; off >>= 1) {
            ax += __shfl_down_sync(0xffffffffu, ax, off);
            ay += __shfl_down_sync(0xffffffffu, ay, off);
            az += __shfl_down_sync(0xffffffffu, az, off);
            aw += __shfl_down_sync(0xffffffffu, aw, off);
        }
        if ((tid & 31) == 0) {
            int w = tid >> 5;
            red[w][0] = ax; red[w][1] = ay; red[w][2] = az; red[w][3] = aw;
        }
        __syncthreads();
        if (tid < 4) {
            float s = 0.f;
#pragma unroll
            for (int w = 0; w < 8; w++) s += red[w][tid];
            out[i * NCLS + tid] = rsqrt_pos(g_rowsum[i]) * s;
        }
        __syncthreads();
    }
}

// ---------------- launch --------------------------------------------------
extern "C" void kernel_launch(void* const* d_in, const int* in_sizes, int n_in,
                              void* d_out, int out_size) {
    const float* x    = (const float*)d_in[0];
    const float* adj  = (const float*)d_in[1];
    const float* xdeg = (const float*)d_in[2];
    const float* ydeg = (const float*)d_in[3];
    const float* Wm1  = (const float*)d_in[4];
    const float* bm1  = (const float*)d_in[5];
    const float* Wm2  = (const float*)d_in[6];
    const float* bm2  = (const float*)d_in[7];
    const float* Wg1  = (const float*)d_in[8];
    const float* Wl2  = (const float*)d_in[9];
    const float* bl2  = (const float*)d_in[10];
    const float* Wg2  = (const float*)d_in[11];

    float* out = (float*)d_out;               // [2048, 4]
    float* hid = out + (size_t)NN * NCLS;     // [2048, 64]

    edge_kernel<<<NN, 256>>>(adj, xdeg, ydeg, Wm1, bm1, Wm2, bm2);
    prep_kernel<<<704, 256>>>(x, Wg1);
    gemm1_kernel<<<dim3(HIDD / BN, NN / BM), 256>>>();
    gemm2_kernel<<<dim3(HIDD / BN, NN / BM), 256>>>();
    hid_kernel<<<NN / 16, 256>>>(Wl2, bl2, Wg2, hid);
    out_kernel<<<NN / 8, 256>>>(out);
}

// round 5
// speedup vs baseline: 2.0921x; 1.0462x over previous
#include <cuda_runtime.h>
#include <cstdint>

#define NN 2048
#define IN_DIM 1024
#define MLPW 16
#define HIDD 256
#define L2DIM 64
#define NCLS 4

// ---------------- scratch (device globals; no allocation) ----------------
__device__ float g_A[(size_t)NN * NN];        // A = adj*mask + I (tf32-rounded)
__device__ float g_Xt[(size_t)NN * IN_DIM];   // tf32-rounded x [2048][1024]
__device__ float g_Bt1[(size_t)HIDD * IN_DIM];// tf32-rounded Wg1 TRANSPOSED [256][1024]
__device__ float g_XWt[(size_t)HIDD * NN];    // dc-scaled x@Wg1 TRANSPOSED [256][2048], tf32
__device__ float g_AXW[(size_t)NN * HIDD];    // dr-scaled A @ XW (fp32) [2048][256]
__device__ float g_HW[(size_t)NN * NCLS];     // dc-scaled hid@Wg2
__device__ float g_rowsum[NN];
__device__ float g_colsum[NN];

__device__ __forceinline__ float rsqrt_pos(float v) {
    return v > 0.f ? rsqrtf(v) : 0.f;
}
__device__ __forceinline__ uint32_t f2tf32(float f) {
    uint32_t u;
    asm("cvt.rna.tf32.f32 %0, %1;" : "=r"(u) : "f"(f));
    return u;
}

// ---------------- async copy / ldmatrix helpers ----------------------------
__device__ __forceinline__ void cp_async16(uint32_t smem, const void* gptr) {
    asm volatile("cp.async.cg.shared.global [%0], [%1], 16;\n" ::"r"(smem), "l"(gptr));
}
__device__ __forceinline__ void cp_commit() {
    asm volatile("cp.async.commit_group;\n");
}
template <int N>
__device__ __forceinline__ void cp_wait() {
    asm volatile("cp.async.wait_group %0;\n" ::"n"(N));
}
__device__ __forceinline__ void ldsm4(uint32_t* r, uint32_t addr) {
    asm volatile("ldmatrix.sync.aligned.m8n8.x4.shared.b16 {%0,%1,%2,%3}, [%4];"
                 : "=r"(r[0]), "=r"(r[1]), "=r"(r[2]), "=r"(r[3]) : "r"(addr));
}
__device__ __forceinline__ void mma_tf32(float* c,
                                         const uint32_t* a,
                                         uint32_t b0, uint32_t b1) {
    asm volatile(
        "mma.sync.aligned.m16n8k8.row.col.f32.tf32.tf32.f32 "
        "{%0,%1,%2,%3}, {%4,%5,%6,%7}, {%8,%9}, {%0,%1,%2,%3};"
        : "+f"(c[0]), "+f"(c[1]), "+f"(c[2]), "+f"(c[3])
        : "r"(a[0]), "r"(a[1]), "r"(a[2]), "r"(a[3]), "r"(b0), "r"(b1));
}

// ---------------- kernel 1: edge MLP -> A (tf32-rounded), rowsum ----------
__global__ __launch_bounds__(256) void edge_kernel(
    const float* __restrict__ adj, const float* __restrict__ xdeg,
    const float* __restrict__ ydeg, const float* __restrict__ Wm1,
    const float* __restrict__ bm1, const float* __restrict__ Wm2,
    const float* __restrict__ bm2) {
    __shared__ float sW1[48], sb1[16], sW2[32], sb2[2];
    int tid = threadIdx.x;
    if (tid < 48) sW1[tid] = Wm1[tid];
    if (tid < 16) sb1[tid] = bm1[tid];
    if (tid < 32) sW2[tid] = Wm2[tid];
    if (tid < 2)  sb2[tid] = bm2[tid];
    int i = blockIdx.x;
    if (tid == 0) g_colsum[i] = 0.f;   // prep_kernel's colsum runs strictly after
    __syncthreads();

    const float* arow = adj  + (size_t)i * NN;
    const float* xrow = xdeg + (size_t)i * NN;
    const float* yrow = ydeg + (size_t)i * NN;
    float* Arow = g_A + (size_t)i * NN;

    float rsum = 0.f;
#pragma unroll
    for (int t = 0; t < NN / 256; t++) {
        int j = tid + t * 256;
        float a = arow[j], xd = xrow[j], yd = yrow[j];
        float l0 = sb2[0], l1 = sb2[1];
#pragma unroll
        for (int k = 0; k < MLPW; k++) {
            float h = fmaf(a, sW1[k], fmaf(xd, sW1[16 + k], fmaf(yd, sW1[32 + k], sb1[k])));
            h = fmaxf(h, 0.f);
            l0 = fmaf(h, sW2[2 * k], l0);
            l1 = fmaf(h, sW2[2 * k + 1], l1);
        }
        float d = 0.5f * (l1 - l0);
        float th;
        asm("tanh.approx.f32 %0, %1;" : "=f"(th) : "f"(d));
        float mask = fmaf(0.5f, th, 0.5f);
        float Av = a * mask + (j == i ? 1.f : 0.f);
        Av = __uint_as_float(f2tf32(Av));
        Arow[j] = Av;
        rsum += Av;
    }
    for (int off = 16; off; off >>= 1) rsum += __shfl_down_sync(0xffffffffu, rsum, off);
    __shared__ float red[8];
    if ((tid & 31) == 0) red[tid >> 5] = rsum;
    __syncthreads();
    if (tid == 0) {
        float s = 0.f;
#pragma unroll
        for (int w = 0; w < 8; w++) s += red[w];
        g_rowsum[i] = s;
    }
}

// ---------------- kernel 2: prep = colsum + round x + transpose-round Wg1 --
// blocks 0..127: colsum; 128..639: round x; 640..895: transpose Wg1 tiles
__global__ __launch_bounds__(256) void prep_kernel(const float* __restrict__ x,
                                                   const float* __restrict__ Wg1) {
    int b = blockIdx.x, tid = threadIdx.x;
    if (b < 128) {
        int j = (b & 7) * 256 + tid;
        int r0 = (b >> 3) * (NN / 16);
        float s = 0.f;
#pragma unroll 4
        for (int i = r0; i < r0 + NN / 16; i++) s += g_A[(size_t)i * NN + j];
        atomicAdd(&g_colsum[j], s);
    } else if (b < 640) {
        size_t idx4 = (size_t)(b - 128) * 1024 + tid;
        const float4* src = reinterpret_cast<const float4*>(x);
        float4* dst = reinterpret_cast<float4*>(g_Xt);
#pragma unroll
        for (int t = 0; t < 4; t++) {
            float4 v = src[idx4 + t * 256];
            uint4 u;
            u.x = f2tf32(v.x); u.y = f2tf32(v.y); u.z = f2tf32(v.z); u.w = f2tf32(v.w);
            dst[idx4 + t * 256] = *reinterpret_cast<float4*>(&u);
        }
    } else {
        // transpose + round Wg1 [1024][256] -> g_Bt1 [256][1024], 32x32 tiles
        __shared__ float s[32][33];
        int t = b - 640;             // 0..255
        int kt = t >> 3;             // 0..31  k-tile
        int nt = t & 7;              // 0..7   n-tile
        int tr = tid >> 3, tc = tid & 7;
        float4 v = *reinterpret_cast<const float4*>(
            &Wg1[(size_t)(kt * 32 + tr) * HIDD + nt * 32 + tc * 4]);
        s[tr][tc * 4 + 0] = __uint_as_float(f2tf32(v.x));
        s[tr][tc * 4 + 1] = __uint_as_float(f2tf32(v.y));
        s[tr][tc * 4 + 2] = __uint_as_float(f2tf32(v.z));
        s[tr][tc * 4 + 3] = __uint_as_float(f2tf32(v.w));
        __syncthreads();
        float4 w;
        w.x = s[tc * 4 + 0][tr];
        w.y = s[tc * 4 + 1][tr];
        w.z = s[tc * 4 + 2][tr];
        w.w = s[tc * 4 + 3][tr];
        *reinterpret_cast<float4*>(
            &g_Bt1[(size_t)(nt * 32 + tr) * IN_DIM + kt * 32 + tc * 4]) = w;
    }
}

// ---------------- tf32 tensor-core GEMM, ldmatrix + intra-CTA K-split ------
// C = rowscale[m] * (A[M x Kd] @ Bt[N x Kd]^T)
// BM=64 BN=64 BK=32, 256 threads; warp (wm, wn, kg): 32x32 tile, kg splits k8.
#define BKK 32
#define NSTG 3
#define STGB 8192   // 64 rows * 128 B

template <bool TRANSOUT>
__device__ __forceinline__ void gemm_body(const float* __restrict__ A,
                                          const float* __restrict__ Bt,
                                          float* __restrict__ C, int Kd,
                                          const float* __restrict__ sumvec) {
    __shared__ __align__(16) uint8_t sAraw[NSTG * STGB];
    __shared__ __align__(16) uint8_t sBraw[NSTG * STGB];
    const uint32_t sAu = (uint32_t)__cvta_generic_to_shared(sAraw);
    const uint32_t sBu = (uint32_t)__cvta_generic_to_shared(sBraw);

    const int tid = threadIdx.x;
    const int lane = tid & 31, warp = tid >> 5;
    const int wm = warp & 1, wn = (warp >> 1) & 1, kg = warp >> 2;
    const int gid = lane >> 2, tig = lane & 3;
    const int mi = lane >> 3, lr = lane & 7;
    const int bm0 = blockIdx.y * 64, bn0 = blockIdx.x * 64;

    // cp.async mapping (identical for A and Bt): 64 rows x 8 quads
    const int ld_row = tid >> 3, ld_q = tid & 7;
    const uint32_t ld_off = ld_row * 128 + ((ld_q ^ (ld_row & 7)) << 4);
    const float* Ap0 = A + (size_t)(bm0 + ld_row) * Kd + ld_q * 4;
    const float* Ap1 = Ap0 + (size_t)32 * Kd;
    const float* Bp0 = Bt + (size_t)(bn0 + ld_row) * Kd + ld_q * 4;
    const float* Bp1 = Bp0 + (size_t)32 * Kd;

    // ldmatrix per-thread addressing
    const int arow = wm * 32 + ((mi & 1) << 3) + lr;       // mt adds 16
    const int brow = wn * 32 + ((mi >> 1) << 3) + lr;      // p adds 16
    const uint32_t axr = arow & 7, bxr = brow & 7;
    const uint32_t qselA = mi >> 1, qselB = mi & 1;
    const uint32_t aOff0 = arow * 128, aOff1 = aOff0 + 16 * 128;
    const uint32_t bOff0 = brow * 128, bOff1 = bOff0 + 16 * 128;

    auto issue = [&](int kt, int s) {
        uint32_t da = sAu + s * STGB + ld_off;
        uint32_t db = sBu + s * STGB + ld_off;
        cp_async16(da, Ap0 + (size_t)kt * BKK);
        cp_async16(da + 4096, Ap1 + (size_t)kt * BKK);
        cp_async16(db, Bp0 + (size_t)kt * BKK);
        cp_async16(db + 4096, Bp1 + (size_t)kt * BKK);
    };

    const int niter = Kd / BKK;
    for (int p = 0; p < NSTG - 1; p++) { issue(p, p); cp_commit(); }

    float acc[2][4][4] = {};

    for (int i = 0; i < niter; i++) {
        cp_wait<NSTG - 2>();
        __syncthreads();
        if (i + NSTG - 1 < niter) issue(i + NSTG - 1, (i + NSTG - 1) % NSTG);
        cp_commit();
        const int s = i % NSTG;
        const uint32_t sAs = sAu + s * STGB, sBs = sBu + s * STGB;
#pragma unroll
        for (int jj = 0; jj < 2; jj++) {
            const uint32_t q2 = ((kg << 1) + jj) << 1;
            const uint32_t aq = ((q2 + qselA) ^ axr) << 4;
            const uint32_t bq = ((q2 + qselB) ^ bxr) << 4;
            uint32_t af0[4], af1[4], bf0[4], bf1[4];
            ldsm4(af0, sAs + aOff0 + aq);
            ldsm4(af1, sAs + aOff1 + aq);
            ldsm4(bf0, sBs + bOff0 + bq);
            ldsm4(bf1, sBs + bOff1 + bq);
            mma_tf32(acc[0][0], af0, bf0[0], bf0[1]);
            mma_tf32(acc[0][1], af0, bf0[2], bf0[3]);
            mma_tf32(acc[0][2], af0, bf1[0], bf1[1]);
            mma_tf32(acc[0][3], af0, bf1[2], bf1[3]);
            mma_tf32(acc[1][0], af1, bf0[0], bf0[1]);
            mma_tf32(acc[1][1], af1, bf0[2], bf0[3]);
            mma_tf32(acc[1][2], af1, bf1[0], bf1[1]);
            mma_tf32(acc[1][3], af1, bf1[2], bf1[3]);
        }
    }

    // ---- intra-CTA K-split reduction through smem (aliases dead stages) ----
    __syncthreads();
    float* sred = reinterpret_cast<float*>(sAraw);   // 4 * 32*33 floats = 16.9KB
    const int pi = wm * 2 + wn;
    if (kg == 1) {
#pragma unroll
        for (int mt = 0; mt < 2; mt++)
#pragma unroll
            for (int nt = 0; nt < 4; nt++) {
                int r = mt * 16 + gid, c = nt * 8 + 2 * tig;
                float* base = sred + pi * 1056;
                base[r * 33 + c] = acc[mt][nt][0];
                base[r * 33 + c + 1] = acc[mt][nt][1];
                base[(r + 8) * 33 + c] = acc[mt][nt][2];
                base[(r + 8) * 33 + c + 1] = acc[mt][nt][3];
            }
    }
    __syncthreads();
    if (kg == 0) {
#pragma unroll
        for (int mt = 0; mt < 2; mt++) {
            int r = mt * 16 + gid;
            const float* base = sred + pi * 1056;
            int gr0 = bm0 + wm * 32 + r;
            int gr1 = gr0 + 8;
            float s0 = rsqrt_pos(sumvec[gr0]);
            float s1 = rsqrt_pos(sumvec[gr1]);
#pragma unroll
            for (int nt = 0; nt < 4; nt++) {
                int c = nt * 8 + 2 * tig;
                float v00 = (acc[mt][nt][0] + base[r * 33 + c]) * s0;
                float v01 = (acc[mt][nt][1] + base[r * 33 + c + 1]) * s0;
                float v10 = (acc[mt][nt][2] + base[(r + 8) * 33 + c]) * s1;
                float v11 = (acc[mt][nt][3] + base[(r + 8) * 33 + c + 1]) * s1;
                if (TRANSOUT) {
                    // C is [N][M] (transposed), tf32-rounded
                    int n0 = bn0 + wn * 32 + c;
                    C[(size_t)n0 * NN + gr0] = __uint_as_float(f2tf32(v00));
                    C[(size_t)(n0 + 1) * NN + gr0] = __uint_as_float(f2tf32(v01));
                    C[(size_t)n0 * NN + gr1] = __uint_as_float(f2tf32(v10));
                    C[(size_t)(n0 + 1) * NN + gr1] = __uint_as_float(f2tf32(v11));
                } else {
                    int col = bn0 + wn * 32 + c;
                    *reinterpret_cast<float2*>(&C[(size_t)gr0 * HIDD + col]) =
                        make_float2(v00, v01);
                    *reinterpret_cast<float2*>(&C[(size_t)gr1 * HIDD + col]) =
                        make_float2(v10, v11);
                }
            }
        }
    }
}

// GEMM1: g_XWt = (dc * (x @ Wg1))^T, tf32-rounded, for gemm2's B operand
__global__ __launch_bounds__(256) void gemm1_kernel() {
    gemm_body<true>(g_Xt, g_Bt1, g_XWt, IN_DIM, g_colsum);
}
// GEMM2: g_AXW = dr * (g_A @ XW), fp32 [2048][256]
__global__ __launch_bounds__(256) void gemm2_kernel() {
    gemm_body<false>(g_A, g_XWt, g_AXW, NN, g_rowsum);
}

// ---------------- hid = AXW @ Wl2 + bl2;  HW = dc * (hid @ Wg2) ------------
__global__ __launch_bounds__(256) void hid_kernel(const float* __restrict__ Wl2,
                                                  const float* __restrict__ bl2,
                                                  const float* __restrict__ Wg2,
                                                  float* __restrict__ hid_out) {
    __shared__ float sAXW[16][HIDD];
    __shared__ float sHid[16][L2DIM + 1];
    int tid = threadIdx.x;
    int rowbase = blockIdx.x * 16;

#pragma unroll
    for (int t = 0; t < 16; t++) {
        int idx = tid + t * 256;
        sAXW[idx >> 8][idx & 255] = g_AXW[(size_t)rowbase * HIDD + idx];
    }
    __syncthreads();

    int c = tid & 63;
    int rq = tid >> 6;
    float acc[4];
    float b = bl2[c];
#pragma unroll
    for (int it = 0; it < 4; it++) acc[it] = b;
#pragma unroll 4
    for (int k = 0; k < HIDD; k++) {
        float w = __ldg(&Wl2[k * L2DIM + c]);
#pragma unroll
        for (int it = 0; it < 4; it++)
            acc[it] = fmaf(sAXW[it * 4 + rq][k], w, acc[it]);
    }
#pragma unroll
    for (int it = 0; it < 4; it++) {
        int row = it * 4 + rq;
        hid_out[(size_t)(rowbase + row) * L2DIM + c] = acc[it];
        sHid[row][c] = acc[it];
    }
    __syncthreads();
    if (tid < 64) {
        int r = tid >> 2, cls = tid & 3;
        float s = 0.f;
#pragma unroll
        for (int k = 0; k < L2DIM; k++) s = fmaf(sHid[r][k], Wg2[k * NCLS + cls], s);
        g_HW[(size_t)(rowbase + r) * NCLS + cls] = s * rsqrt_pos(g_colsum[rowbase + r]);
    }
}

// ---------------- out[i] = dr[i] * sum_j A[i,j] * HW[j] --------------------
__global__ __launch_bounds__(256) void out_kernel(float* __restrict__ out) {
    int tid = threadIdx.x;
    __shared__ float4 sHW[NN];
    const float4* hw4 = reinterpret_cast<const float4*>(g_HW);
#pragma unroll
    for (int t = 0; t < NN / 256; t++) sHW[tid + t * 256] = hw4[tid + t * 256];
    __syncthreads();

    __shared__ float red[8][4];
    for (int r = 0; r < 8; r++) {
        int i = blockIdx.x * 8 + r;
        const float* arow = g_A + (size_t)i * NN;
        float ax = 0.f, ay = 0.f, az = 0.f, aw = 0.f;
#pragma unroll
        for (int t = 0; t < NN / 256; t++) {
            int j = tid + t * 256;
            float a = arow[j];
            float4 h = sHW[j];
            ax = fmaf(a, h.x, ax);
            ay = fmaf(a, h.y, ay);
            az = fmaf(a, h.z, az);
            aw = fmaf(a, h.w, aw);
        }
        for (int off = 16; off; off >>= 1) {
            ax += __shfl_down_sync(0xffffffffu, ax, off);
            ay += __shfl_down_sync(0xffffffffu, ay, off);
            az += __shfl_down_sync(0xffffffffu, az, off);
            aw += __shfl_down_sync(0xffffffffu, aw, off);
        }
        if ((tid & 31) == 0) {
            int w = tid >> 5;
            red[w][0] = ax; red[w][1] = ay; red[w][2] = az; red[w][3] = aw;
        }
        __syncthreads();
        if (tid < 4) {
            float s = 0.f;
#pragma unroll
            for (int w = 0; w < 8; w++) s += red[w][tid];
            out[i * NCLS + tid] = rsqrt_pos(g_rowsum[i]) * s;
        }
        __syncthreads();
    }
}

// ---------------- launch --------------------------------------------------
extern "C" void kernel_launch(void* const* d_in, const int* in_sizes, int n_in,
                              void* d_out, int out_size) {
    const float* x    = (const float*)d_in[0];
    const float* adj  = (const float*)d_in[1];
    const float* xdeg = (const float*)d_in[2];
    const float* ydeg = (const float*)d_in[3];
    const float* Wm1  = (const float*)d_in[4];
    const float* bm1  = (const float*)d_in[5];
    const float* Wm2  = (const float*)d_in[6];
    const float* bm2  = (const float*)d_in[7];
    const float* Wg1  = (const float*)d_in[8];
    const float* Wl2  = (const float*)d_in[9];
    const float* bl2  = (const float*)d_in[10];
    const float* Wg2  = (const float*)d_in[11];

    float* out = (float*)d_out;               // [2048, 4]
    float* hid = out + (size_t)NN * NCLS;     // [2048, 64]

    edge_kernel<<<NN, 256>>>(adj, xdeg, ydeg, Wm1, bm1, Wm2, bm2);
    prep_kernel<<<896, 256>>>(x, Wg1);
    gemm1_kernel<<<dim3(HIDD / 64, NN / 64), 256>>>();
    gemm2_kernel<<<dim3(HIDD / 64, NN / 64), 256>>>();
    hid_kernel<<<NN / 16, 256>>>(Wl2, bl2, Wg2, hid);
    out_kernel<<<NN / 8, 256>>>(out);
}

// round 6
// speedup vs baseline: 2.1124x; 1.0097x over previous
#include <cuda_runtime.h>
#include <cstdint>

#define NN 2048
#define IN_DIM 1024
#define MLPW 16
#define HIDD 256
#define L2DIM 64
#define NCLS 4

// ---------------- scratch (device globals; no allocation) ----------------
__device__ float g_A[(size_t)NN * NN];        // A = adj*mask + I (tf32-rounded)
__device__ float g_Xt[(size_t)NN * IN_DIM];   // tf32-rounded x [2048][1024]
__device__ float g_Bt1[(size_t)HIDD * IN_DIM];// tf32-rounded Wg1 TRANSPOSED [256][1024]
__device__ float g_XWt[(size_t)HIDD * NN];    // dc-scaled x@Wg1 TRANSPOSED [256][2048], tf32
__device__ float g_AXW[(size_t)NN * HIDD];    // dr-scaled A @ XW (fp32) [2048][256]
__device__ float g_HW[(size_t)NN * NCLS];     // dc-scaled hid@Wg2
__device__ float g_rowsum[NN];
__device__ float g_colsum[NN];

__device__ __forceinline__ float rsqrt_pos(float v) {
    return v > 0.f ? rsqrtf(v) : 0.f;
}
__device__ __forceinline__ uint32_t f2tf32(float f) {
    uint32_t u;
    asm("cvt.rna.tf32.f32 %0, %1;" : "=r"(u) : "f"(f));
    return u;
}

// ---------------- async copy / ldmatrix helpers ----------------------------
__device__ __forceinline__ void cp_async16(uint32_t smem, const void* gptr) {
    asm volatile("cp.async.cg.shared.global [%0], [%1], 16;\n" ::"r"(smem), "l"(gptr));
}
__device__ __forceinline__ void cp_commit() {
    asm volatile("cp.async.commit_group;\n");
}
template <int N>
__device__ __forceinline__ void cp_wait() {
    asm volatile("cp.async.wait_group %0;\n" ::"n"(N));
}
__device__ __forceinline__ void ldsm4(uint32_t* r, uint32_t addr) {
    asm volatile("ldmatrix.sync.aligned.m8n8.x4.shared.b16 {%0,%1,%2,%3}, [%4];"
                 : "=r"(r[0]), "=r"(r[1]), "=r"(r[2]), "=r"(r[3]) : "r"(addr));
}
__device__ __forceinline__ void mma_tf32(float* c,
                                         const uint32_t* a,
                                         uint32_t b0, uint32_t b1) {
    asm volatile(
        "mma.sync.aligned.m16n8k8.row.col.f32.tf32.tf32.f32 "
        "{%0,%1,%2,%3}, {%4,%5,%6,%7}, {%8,%9}, {%0,%1,%2,%3};"
        : "+f"(c[0]), "+f"(c[1]), "+f"(c[2]), "+f"(c[3])
        : "r"(a[0]), "r"(a[1]), "r"(a[2]), "r"(a[3]), "r"(b0), "r"(b1));
}

// ---------------- kernel 1: edge MLP -> A (tf32-rounded), rowsum ----------
__global__ __launch_bounds__(256) void edge_kernel(
    const float* __restrict__ adj, const float* __restrict__ xdeg,
    const float* __restrict__ ydeg, const float* __restrict__ Wm1,
    const float* __restrict__ bm1, const float* __restrict__ Wm2,
    const float* __restrict__ bm2) {
    __shared__ float sW1[48], sb1[16], sW2[32], sb2[2];
    int tid = threadIdx.x;
    if (tid < 48) sW1[tid] = Wm1[tid];
    if (tid < 16) sb1[tid] = bm1[tid];
    if (tid < 32) sW2[tid] = Wm2[tid];
    if (tid < 2)  sb2[tid] = bm2[tid];
    int i = blockIdx.x;
    if (tid == 0) g_colsum[i] = 0.f;   // prep_kernel's colsum runs strictly after
    __syncthreads();

    const float* arow = adj  + (size_t)i * NN;
    const float* xrow = xdeg + (size_t)i * NN;
    const float* yrow = ydeg + (size_t)i * NN;
    float* Arow = g_A + (size_t)i * NN;

    float rsum = 0.f;
#pragma unroll
    for (int t = 0; t < NN / 256; t++) {
        int j = tid + t * 256;
        float a = arow[j], xd = xrow[j], yd = yrow[j];
        float l0 = sb2[0], l1 = sb2[1];
#pragma unroll
        for (int k = 0; k < MLPW; k++) {
            float h = fmaf(a, sW1[k], fmaf(xd, sW1[16 + k], fmaf(yd, sW1[32 + k], sb1[k])));
            h = fmaxf(h, 0.f);
            l0 = fmaf(h, sW2[2 * k], l0);
            l1 = fmaf(h, sW2[2 * k + 1], l1);
        }
        float d = 0.5f * (l1 - l0);
        float th;
        asm("tanh.approx.f32 %0, %1;" : "=f"(th) : "f"(d));
        float mask = fmaf(0.5f, th, 0.5f);
        float Av = a * mask + (j == i ? 1.f : 0.f);
        Av = __uint_as_float(f2tf32(Av));
        Arow[j] = Av;
        rsum += Av;
    }
    for (int off = 16; off; off >>= 1) rsum += __shfl_down_sync(0xffffffffu, rsum, off);
    __shared__ float red[8];
    if ((tid & 31) == 0) red[tid >> 5] = rsum;
    __syncthreads();
    if (tid == 0) {
        float s = 0.f;
#pragma unroll
        for (int w = 0; w < 8; w++) s += red[w];
        g_rowsum[i] = s;
    }
}

// ---------------- kernel 2: prep = colsum + round x + transpose-round Wg1 --
__global__ __launch_bounds__(256) void prep_kernel(const float* __restrict__ x,
                                                   const float* __restrict__ Wg1) {
    int b = blockIdx.x, tid = threadIdx.x;
    if (b < 128) {
        int j = (b & 7) * 256 + tid;
        int r0 = (b >> 3) * (NN / 16);
        float s = 0.f;
#pragma unroll 4
        for (int i = r0; i < r0 + NN / 16; i++) s += g_A[(size_t)i * NN + j];
        atomicAdd(&g_colsum[j], s);
    } else if (b < 640) {
        size_t idx4 = (size_t)(b - 128) * 1024 + tid;
        const float4* src = reinterpret_cast<const float4*>(x);
        float4* dst = reinterpret_cast<float4*>(g_Xt);
#pragma unroll
        for (int t = 0; t < 4; t++) {
            float4 v = src[idx4 + t * 256];
            uint4 u;
            u.x = f2tf32(v.x); u.y = f2tf32(v.y); u.z = f2tf32(v.z); u.w = f2tf32(v.w);
            dst[idx4 + t * 256] = *reinterpret_cast<float4*>(&u);
        }
    } else {
        // transpose + round Wg1 [1024][256] -> g_Bt1 [256][1024], 32x32 tiles
        __shared__ float s[32][33];
        int t = b - 640;             // 0..255
        int kt = t >> 3;             // 0..31  k-tile
        int nt = t & 7;              // 0..7   n-tile
        int tr = tid >> 3, tc = tid & 7;
        float4 v = *reinterpret_cast<const float4*>(
            &Wg1[(size_t)(kt * 32 + tr) * HIDD + nt * 32 + tc * 4]);
        s[tr][tc * 4 + 0] = __uint_as_float(f2tf32(v.x));
        s[tr][tc * 4 + 1] = __uint_as_float(f2tf32(v.y));
        s[tr][tc * 4 + 2] = __uint_as_float(f2tf32(v.z));
        s[tr][tc * 4 + 3] = __uint_as_float(f2tf32(v.w));
        __syncthreads();
        float4 w;
        w.x = s[tc * 4 + 0][tr];
        w.y = s[tc * 4 + 1][tr];
        w.z = s[tc * 4 + 2][tr];
        w.w = s[tc * 4 + 3][tr];
        *reinterpret_cast<float4*>(
            &g_Bt1[(size_t)(nt * 32 + tr) * IN_DIM + kt * 32 + tc * 4]) = w;
    }
}

// ---------------- tf32 tensor-core GEMM, 512 threads, 4-way K-split --------
// C = rowscale[m] * (A[M x Kd] @ Bt[N x Kd]^T)
// BM=64 BN=64 BK=32; warp (wm, wn, kg): 32x32 tile, kg in {0..3} takes one k8
// slice per stage. Partials combined via smem atomicAdd, kg=0 writes out.
#define BKK 32
#define NSTG 3
#define STGB 8192   // 64 rows * 128 B
#define RPITCH 66

template <bool TRANSOUT>
__device__ __forceinline__ void gemm_body(const float* __restrict__ A,
                                          const float* __restrict__ Bt,
                                          float* __restrict__ C, int Kd,
                                          const float* __restrict__ sumvec) {
    __shared__ __align__(16) uint8_t sAraw[NSTG * STGB];
    __shared__ __align__(16) uint8_t sBraw[NSTG * STGB];
    const uint32_t sAu = (uint32_t)__cvta_generic_to_shared(sAraw);
    const uint32_t sBu = (uint32_t)__cvta_generic_to_shared(sBraw);

    const int tid = threadIdx.x;
    const int lane = tid & 31, warp = tid >> 5;
    const int wm = warp & 1, wn = (warp >> 1) & 1, kg = warp >> 2;  // kg 0..3
    const int gid = lane >> 2, tig = lane & 3;
    const int mi = lane >> 3, lr = lane & 7;
    const int bm0 = blockIdx.y * 64, bn0 = blockIdx.x * 64;

    // cp.async mapping: 512 threads, each loads one 16B chunk of A and of B
    const int ld_row = tid >> 3, ld_q = tid & 7;
    const uint32_t ld_off = ld_row * 128 + ((ld_q ^ (ld_row & 7)) << 4);
    const float* Ap = A + (size_t)(bm0 + ld_row) * Kd + ld_q * 4;
    const float* Bp = Bt + (size_t)(bn0 + ld_row) * Kd + ld_q * 4;

    // ldmatrix per-thread addressing
    const int arow = wm * 32 + ((mi & 1) << 3) + lr;
    const int brow = wn * 32 + ((mi >> 1) << 3) + lr;
    const uint32_t axr = arow & 7, bxr = brow & 7;
    const uint32_t qselA = mi >> 1, qselB = mi & 1;
    const uint32_t aOff0 = arow * 128, aOff1 = aOff0 + 16 * 128;
    const uint32_t bOff0 = brow * 128, bOff1 = bOff0 + 16 * 128;
    const uint32_t q2 = kg << 1;                    // this warp's k8 slice
    const uint32_t aq = ((q2 + qselA) ^ axr) << 4;
    const uint32_t bq = ((q2 + qselB) ^ bxr) << 4;

    auto issue = [&](int kt, int s) {
        cp_async16(sAu + s * STGB + ld_off, Ap + (size_t)kt * BKK);
        cp_async16(sBu + s * STGB + ld_off, Bp + (size_t)kt * BKK);
    };

    const int niter = Kd / BKK;
    for (int p = 0; p < NSTG - 1; p++) { issue(p, p); cp_commit(); }

    float acc[2][4][4] = {};

    for (int i = 0; i < niter; i++) {
        cp_wait<NSTG - 2>();
        __syncthreads();
        if (i + NSTG - 1 < niter) issue(i + NSTG - 1, (i + NSTG - 1) % NSTG);
        cp_commit();
        const int s = i % NSTG;
        const uint32_t sAs = sAu + s * STGB, sBs = sBu + s * STGB;
        uint32_t af0[4], af1[4], bf0[4], bf1[4];
        ldsm4(af0, sAs + aOff0 + aq);
        ldsm4(af1, sAs + aOff1 + aq);
        ldsm4(bf0, sBs + bOff0 + bq);
        ldsm4(bf1, sBs + bOff1 + bq);
        mma_tf32(acc[0][0], af0, bf0[0], bf0[1]);
        mma_tf32(acc[0][1], af0, bf0[2], bf0[3]);
        mma_tf32(acc[0][2], af0, bf1[0], bf1[1]);
        mma_tf32(acc[0][3], af0, bf1[2], bf1[3]);
        mma_tf32(acc[1][0], af1, bf0[0], bf0[1]);
        mma_tf32(acc[1][1], af1, bf0[2], bf0[3]);
        mma_tf32(acc[1][2], af1, bf1[0], bf1[1]);
        mma_tf32(acc[1][3], af1, bf1[2], bf1[3]);
    }

    // ---- 4-way K-split reduction through smem (aliases dead stages) -------
    __syncthreads();
    float* sred = reinterpret_cast<float*>(sAraw);   // 64 x RPITCH floats < 24KB
    // kg=0 seeds the buffer
    if (kg == 0) {
#pragma unroll
        for (int mt = 0; mt < 2; mt++)
#pragma unroll
            for (int nt = 0; nt < 4; nt++) {
                int r = wm * 32 + mt * 16 + gid;
                int c = wn * 32 + nt * 8 + 2 * tig;
                sred[r * RPITCH + c] = acc[mt][nt][0];
                sred[r * RPITCH + c + 1] = acc[mt][nt][1];
                sred[(r + 8) * RPITCH + c] = acc[mt][nt][2];
                sred[(r + 8) * RPITCH + c + 1] = acc[mt][nt][3];
            }
    }
    __syncthreads();
    if (kg != 0) {
#pragma unroll
        for (int mt = 0; mt < 2; mt++)
#pragma unroll
            for (int nt = 0; nt < 4; nt++) {
                int r = wm * 32 + mt * 16 + gid;
                int c = wn * 32 + nt * 8 + 2 * tig;
                atomicAdd(&sred[r * RPITCH + c], acc[mt][nt][0]);
                atomicAdd(&sred[r * RPITCH + c + 1], acc[mt][nt][1]);
                atomicAdd(&sred[(r + 8) * RPITCH + c], acc[mt][nt][2]);
                atomicAdd(&sred[(r + 8) * RPITCH + c + 1], acc[mt][nt][3]);
            }
    }
    __syncthreads();
    if (kg == 0) {
#pragma unroll
        for (int mt = 0; mt < 2; mt++) {
            int r = wm * 32 + mt * 16 + gid;
            int gr0 = bm0 + r, gr1 = gr0 + 8;
            float s0 = rsqrt_pos(sumvec[gr0]);
            float s1 = rsqrt_pos(sumvec[gr1]);
#pragma unroll
            for (int nt = 0; nt < 4; nt++) {
                int c = wn * 32 + nt * 8 + 2 * tig;
                float v00 = sred[r * RPITCH + c] * s0;
                float v01 = sred[r * RPITCH + c + 1] * s0;
                float v10 = sred[(r + 8) * RPITCH + c] * s1;
                float v11 = sred[(r + 8) * RPITCH + c + 1] * s1;
                if (TRANSOUT) {
                    int n0 = bn0 + c;
                    C[(size_t)n0 * NN + gr0] = __uint_as_float(f2tf32(v00));
                    C[(size_t)(n0 + 1) * NN + gr0] = __uint_as_float(f2tf32(v01));
                    C[(size_t)n0 * NN + gr1] = __uint_as_float(f2tf32(v10));
                    C[(size_t)(n0 + 1) * NN + gr1] = __uint_as_float(f2tf32(v11));
                } else {
                    int col = bn0 + c;
                    *reinterpret_cast<float2*>(&C[(size_t)gr0 * HIDD + col]) =
                        make_float2(v00, v01);
                    *reinterpret_cast<float2*>(&C[(size_t)gr1 * HIDD + col]) =
                        make_float2(v10, v11);
                }
            }
        }
    }
}

// GEMM1: g_XWt = (dc * (x @ Wg1))^T, tf32-rounded, for gemm2's B operand
__global__ __launch_bounds__(512) void gemm1_kernel() {
    gemm_body<true>(g_Xt, g_Bt1, g_XWt, IN_DIM, g_colsum);
}
// GEMM2: g_AXW = dr * (g_A @ XW), fp32 [2048][256]
__global__ __launch_bounds__(512) void gemm2_kernel() {
    gemm_body<false>(g_A, g_XWt, g_AXW, NN, g_rowsum);
}

// ---------------- hid = AXW @ Wl2 + bl2;  HW = dc * (hid @ Wg2) ------------
__global__ __launch_bounds__(256) void hid_kernel(const float* __restrict__ Wl2,
                                                  const float* __restrict__ bl2,
                                                  const float* __restrict__ Wg2,
                                                  float* __restrict__ hid_out) {
    __shared__ float sAXW[16][HIDD];
    __shared__ float sHid[16][L2DIM + 1];
    int tid = threadIdx.x;
    int rowbase = blockIdx.x * 16;

#pragma unroll
    for (int t = 0; t < 16; t++) {
        int idx = tid + t * 256;
        sAXW[idx >> 8][idx & 255] = g_AXW[(size_t)rowbase * HIDD + idx];
    }
    __syncthreads();

    int c = tid & 63;
    int rq = tid >> 6;
    float acc[4];
    float b = bl2[c];
#pragma unroll
    for (int it = 0; it < 4; it++) acc[it] = b;
#pragma unroll 4
    for (int k = 0; k < HIDD; k++) {
        float w = __ldg(&Wl2[k * L2DIM + c]);
#pragma unroll
        for (int it = 0; it < 4; it++)
            acc[it] = fmaf(sAXW[it * 4 + rq][k], w, acc[it]);
    }
#pragma unroll
    for (int it = 0; it < 4; it++) {
        int row = it * 4 + rq;
        hid_out[(size_t)(rowbase + row) * L2DIM + c] = acc[it];
        sHid[row][c] = acc[it];
    }
    __syncthreads();
    if (tid < 64) {
        int r = tid >> 2, cls = tid & 3;
        float s = 0.f;
#pragma unroll
        for (int k = 0; k < L2DIM; k++) s = fmaf(sHid[r][k], Wg2[k * NCLS + cls], s);
        g_HW[(size_t)(rowbase + r) * NCLS + cls] = s * rsqrt_pos(g_colsum[rowbase + r]);
    }
}

// ---------------- out[i] = dr[i] * sum_j A[i,j] * HW[j] --------------------
__global__ __launch_bounds__(256) void out_kernel(float* __restrict__ out) {
    int tid = threadIdx.x;
    __shared__ float4 sHW[NN];
    const float4* hw4 = reinterpret_cast<const float4*>(g_HW);
#pragma unroll
    for (int t = 0; t < NN / 256; t++) sHW[tid + t * 256] = hw4[tid + t * 256];
    __syncthreads();

    __shared__ float red[8][4];
    for (int r = 0; r < 8; r++) {
        int i = blockIdx.x * 8 + r;
        const float* arow = g_A + (size_t)i * NN;
        float ax = 0.f, ay = 0.f, az = 0.f, aw = 0.f;
#pragma unroll
        for (int t = 0; t < NN / 256; t++) {
            int j = tid + t * 256;
            float a = arow[j];
            float4 h = sHW[j];
            ax = fmaf(a, h.x, ax);
            ay = fmaf(a, h.y, ay);
            az = fmaf(a, h.z, az);
            aw = fmaf(a, h.w, aw);
        }
        for (int off = 16; off; off >>= 1) {
            ax += __shfl_down_sync(0xffffffffu, ax, off);
            ay += __shfl_down_sync(0xffffffffu, ay, off);
            az += __shfl_down_sync(0xffffffffu, az, off);
            aw += __shfl_down_sync(0xffffffffu, aw, off);
        }
        if ((tid & 31) == 0) {
            int w = tid >> 5;
            red[w][0] = ax; red[w][1] = ay; red[w][2] = az; red[w][3] = aw;
        }
        __syncthreads();
        if (tid < 4) {
            float s = 0.f;
#pragma unroll
            for (int w = 0; w < 8; w++) s += red[w][tid];
            out[i * NCLS + tid] = rsqrt_pos(g_rowsum[i]) * s;
        }
        __syncthreads();
    }
}

// ---------------- launch --------------------------------------------------
extern "C" void kernel_launch(void* const* d_in, const int* in_sizes, int n_in,
                              void* d_out, int out_size) {
    const float* x    = (const float*)d_in[0];
    const float* adj  = (const float*)d_in[1];
    const float* xdeg = (const float*)d_in[2];
    const float* ydeg = (const float*)d_in[3];
    const float* Wm1  = (const float*)d_in[4];
    const float* bm1  = (const float*)d_in[5];
    const float* Wm2  = (const float*)d_in[6];
    const float* bm2  = (const float*)d_in[7];
    const float* Wg1  = (const float*)d_in[8];
    const float* Wl2  = (const float*)d_in[9];
    const float* bl2  = (const float*)d_in[10];
    const float* Wg2  = (const float*)d_in[11];

    float* out = (float*)d_out;               // [2048, 4]
    float* hid = out + (size_t)NN * NCLS;     // [2048, 64]

    edge_kernel<<<NN, 256>>>(adj, xdeg, ydeg, Wm1, bm1, Wm2, bm2);
    prep_kernel<<<896, 256>>>(x, Wg1);
    gemm1_kernel<<<dim3(HIDD / 64, NN / 64), 512>>>();
    gemm2_kernel<<<dim3(HIDD / 64, NN / 64), 512>>>();
    hid_kernel<<<NN / 16, 256>>>(Wl2, bl2, Wg2, hid);
    out_kernel<<<NN / 8, 256>>>(out);
}

// round 7
// speedup vs baseline: 2.1528x; 1.0191x over previous
#include <cuda_runtime.h>
#include <cstdint>

#define NN 2048
#define IN_DIM 1024
#define MLPW 16
#define HIDD 256
#define L2DIM 64
#define NCLS 4

// ---------------- scratch (device globals; no allocation) ----------------
__device__ float g_A[(size_t)NN * NN];        // A = adj*mask + I (tf32-rounded)
__device__ float g_Xt[(size_t)NN * IN_DIM];   // tf32-rounded x [2048][1024]
__device__ float g_Bt1[(size_t)HIDD * IN_DIM];// tf32-rounded Wg1 TRANSPOSED [256][1024]
__device__ float g_XWt[(size_t)HIDD * NN];    // dc-scaled x@Wg1 TRANSPOSED [256][2048], tf32
__device__ float g_AXW[4][(size_t)NN * HIDD]; // dr-scaled A@XW split-K partials (fp32)
__device__ float g_HW[(size_t)NN * NCLS];     // dc-scaled hid@Wg2
__device__ float g_rowsum[NN];
__device__ float g_colsum[NN];

__device__ __forceinline__ float rsqrt_pos(float v) {
    return v > 0.f ? rsqrtf(v) : 0.f;
}
__device__ __forceinline__ uint32_t f2tf32(float f) {
    uint32_t u;
    asm("cvt.rna.tf32.f32 %0, %1;" : "=r"(u) : "f"(f));
    return u;
}

// ---------------- async copy / ldmatrix helpers ----------------------------
__device__ __forceinline__ void cp_async16(uint32_t smem, const void* gptr) {
    asm volatile("cp.async.cg.shared.global [%0], [%1], 16;\n" ::"r"(smem), "l"(gptr));
}
__device__ __forceinline__ void cp_commit() {
    asm volatile("cp.async.commit_group;\n");
}
template <int N>
__device__ __forceinline__ void cp_wait() {
    asm volatile("cp.async.wait_group %0;\n" ::"n"(N));
}
__device__ __forceinline__ void ldsm4(uint32_t* r, uint32_t addr) {
    asm volatile("ldmatrix.sync.aligned.m8n8.x4.shared.b16 {%0,%1,%2,%3}, [%4];"
                 : "=r"(r[0]), "=r"(r[1]), "=r"(r[2]), "=r"(r[3]) : "r"(addr));
}
__device__ __forceinline__ void mma_tf32(float* c,
                                         const uint32_t* a,
                                         uint32_t b0, uint32_t b1) {
    asm volatile(
        "mma.sync.aligned.m16n8k8.row.col.f32.tf32.tf32.f32 "
        "{%0,%1,%2,%3}, {%4,%5,%6,%7}, {%8,%9}, {%0,%1,%2,%3};"
        : "+f"(c[0]), "+f"(c[1]), "+f"(c[2]), "+f"(c[3])
        : "r"(a[0]), "r"(a[1]), "r"(a[2]), "r"(a[3]), "r"(b0), "r"(b1));
}

// ---------------- kernel 1: edge MLP -> A (tf32-rounded), rowsum ----------
__global__ __launch_bounds__(256) void edge_kernel(
    const float* __restrict__ adj, const float* __restrict__ xdeg,
    const float* __restrict__ ydeg, const float* __restrict__ Wm1,
    const float* __restrict__ bm1, const float* __restrict__ Wm2,
    const float* __restrict__ bm2) {
    __shared__ float sW1[48], sb1[16], sdw[16], sb2[2];
    int tid = threadIdx.x;
    if (tid < 48) sW1[tid] = Wm1[tid];
    if (tid < 16) sb1[tid] = bm1[tid];
    if (tid < 16) sdw[tid] = Wm2[2 * tid + 1] - Wm2[2 * tid];
    if (tid < 2)  sb2[tid] = bm2[tid];
    int i = blockIdx.x;
    if (tid == 0) g_colsum[i] = 0.f;   // prep_kernel's colsum runs strictly after
    __syncthreads();

    const float* arow = adj  + (size_t)i * NN;
    const float* xrow = xdeg + (size_t)i * NN;
    const float* yrow = ydeg + (size_t)i * NN;
    float* Arow = g_A + (size_t)i * NN;
    const float db = sb2[1] - sb2[0];

    float rsum = 0.f;
#pragma unroll
    for (int t = 0; t < NN / 256; t++) {
        int j = tid + t * 256;
        float a = arow[j], xd = xrow[j], yd = yrow[j];
        float dl = db;
#pragma unroll
        for (int k = 0; k < MLPW; k++) {
            float h = fmaf(a, sW1[k], fmaf(xd, sW1[16 + k], fmaf(yd, sW1[32 + k], sb1[k])));
            h = fmaxf(h, 0.f);
            dl = fmaf(h, sdw[k], dl);
        }
        float d = 0.5f * dl;
        float th;
        asm("tanh.approx.f32 %0, %1;" : "=f"(th) : "f"(d));
        float mask = fmaf(0.5f, th, 0.5f);
        float Av = a * mask + (j == i ? 1.f : 0.f);
        Av = __uint_as_float(f2tf32(Av));
        Arow[j] = Av;
        rsum += Av;
    }
    for (int off = 16; off; off >>= 1) rsum += __shfl_down_sync(0xffffffffu, rsum, off);
    __shared__ float red[8];
    if ((tid & 31) == 0) red[tid >> 5] = rsum;
    __syncthreads();
    if (tid == 0) {
        float s = 0.f;
#pragma unroll
        for (int w = 0; w < 8; w++) s += red[w];
        g_rowsum[i] = s;
    }
}

// ---------------- kernel 2: prep = colsum + round x + transpose-round Wg1 --
__global__ __launch_bounds__(256) void prep_kernel(const float* __restrict__ x,
                                                   const float* __restrict__ Wg1) {
    int b = blockIdx.x, tid = threadIdx.x;
    if (b < 128) {
        int j = (b & 7) * 256 + tid;
        int r0 = (b >> 3) * (NN / 16);
        float s = 0.f;
#pragma unroll 4
        for (int i = r0; i < r0 + NN / 16; i++) s += g_A[(size_t)i * NN + j];
        atomicAdd(&g_colsum[j], s);
    } else if (b < 640) {
        size_t idx4 = (size_t)(b - 128) * 1024 + tid;
        const float4* src = reinterpret_cast<const float4*>(x);
        float4* dst = reinterpret_cast<float4*>(g_Xt);
#pragma unroll
        for (int t = 0; t < 4; t++) {
            float4 v = src[idx4 + t * 256];
            uint4 u;
            u.x = f2tf32(v.x); u.y = f2tf32(v.y); u.z = f2tf32(v.z); u.w = f2tf32(v.w);
            dst[idx4 + t * 256] = *reinterpret_cast<float4*>(&u);
        }
    } else {
        // transpose + round Wg1 [1024][256] -> g_Bt1 [256][1024], 32x32 tiles
        __shared__ float s[32][33];
        int t = b - 640;             // 0..255
        int kt = t >> 3;             // 0..31  k-tile
        int nt = t & 7;              // 0..7   n-tile
        int tr = tid >> 3, tc = tid & 7;
        float4 v = *reinterpret_cast<const float4*>(
            &Wg1[(size_t)(kt * 32 + tr) * HIDD + nt * 32 + tc * 4]);
        s[tr][tc * 4 + 0] = __uint_as_float(f2tf32(v.x));
        s[tr][tc * 4 + 1] = __uint_as_float(f2tf32(v.y));
        s[tr][tc * 4 + 2] = __uint_as_float(f2tf32(v.z));
        s[tr][tc * 4 + 3] = __uint_as_float(f2tf32(v.w));
        __syncthreads();
        float4 w;
        w.x = s[tc * 4 + 0][tr];
        w.y = s[tc * 4 + 1][tr];
        w.z = s[tc * 4 + 2][tr];
        w.w = s[tc * 4 + 3][tr];
        *reinterpret_cast<float4*>(
            &g_Bt1[(size_t)(nt * 32 + tr) * IN_DIM + kt * 32 + tc * 4]) = w;
    }
}

// ---------------- tf32 tensor-core GEMM, BK=64, 2-stage, split-K CTAs -----
// C = rowscale[m] * (A[M x Kd] @ Bt[N x Kd]^T), K chunk per CTA = Kd/NSPLIT
// BM=64 BN=64 BK=64 (two 8KB halves/operand); 256 threads, warps (wm,wn,kg),
// kg in {0,1} splits the 8 k8-slices; partials merged via smem.
#define BKK 64
#define HSB 8192      // half-stage bytes per operand (64 rows * 128B)
#define OPB 16384     // per-stage per-operand bytes
#define GEMM_SMEM 65536

template <bool TRANSOUT, int NSPLIT>
__device__ __forceinline__ void gemm_body(const float* __restrict__ A,
                                          const float* __restrict__ Bt,
                                          float* __restrict__ C, int Kd,
                                          const float* __restrict__ sumvec) {
    extern __shared__ __align__(16) uint8_t smem_dyn[];
    const uint32_t sAu = (uint32_t)__cvta_generic_to_shared(smem_dyn);
    const uint32_t sBu = sAu + 2 * OPB;

    const int tid = threadIdx.x;
    const int lane = tid & 31, warp = tid >> 5;
    const int wm = warp & 1, wn = (warp >> 1) & 1, kg = warp >> 2;  // kg 0..1
    const int gid = lane >> 2, tig = lane & 3;
    const int mi = lane >> 3, lr = lane & 7;
    const int bm0 = blockIdx.y * 64, bn0 = blockIdx.x * 64;
    const int kbase = (NSPLIT > 1) ? blockIdx.z * (Kd / NSPLIT) : 0;

    // loader: 256 threads, each covers 2 quads of one row per operand-half
    const int ld_row = tid >> 2;           // 0..63
    const int qb = (tid & 3) << 1;         // 0,2,4,6
    const uint32_t off0 = ld_row * 128 + (((qb + 0) ^ (ld_row & 7)) << 4);
    const uint32_t off1 = ld_row * 128 + (((qb + 1) ^ (ld_row & 7)) << 4);
    const float* Ag = A + (size_t)(bm0 + ld_row) * Kd + kbase;
    const float* Bg = Bt + (size_t)(bn0 + ld_row) * Kd + kbase;

    // ldmatrix per-thread addressing
    const int arow = wm * 32 + ((mi & 1) << 3) + lr;
    const int brow = wn * 32 + ((mi >> 1) << 3) + lr;
    const uint32_t axr = arow & 7, bxr = brow & 7;
    const uint32_t qselA = mi >> 1, qselB = mi & 1;
    const uint32_t aOff0 = arow * 128, aOff1 = aOff0 + 16 * 128;
    const uint32_t bOff0 = brow * 128, bOff1 = bOff0 + 16 * 128;
    // the two k8 slices (within a half) this warp owns: q2 = (2*kg+jj)*2
    const uint32_t aqj[2] = {(((uint32_t)(kg * 2 + 0) * 2 + qselA) ^ axr) << 4,
                             (((uint32_t)(kg * 2 + 1) * 2 + qselA) ^ axr) << 4};
    const uint32_t bqj[2] = {(((uint32_t)(kg * 2 + 0) * 2 + qselB) ^ bxr) << 4,
                             (((uint32_t)(kg * 2 + 1) * 2 + qselB) ^ bxr) << 4};

    auto issue = [&](int kt, int s) {
#pragma unroll
        for (int h = 0; h < 2; h++) {
            const float* ag = Ag + (size_t)kt * BKK + h * 32;
            const float* bg = Bg + (size_t)kt * BKK + h * 32;
            uint32_t da = sAu + s * OPB + h * HSB;
            uint32_t db = sBu + s * OPB + h * HSB;
            cp_async16(da + off0, ag + qb * 4);
            cp_async16(da + off1, ag + qb * 4 + 4);
            cp_async16(db + off0, bg + qb * 4);
            cp_async16(db + off1, bg + qb * 4 + 4);
        }
    };

    const int niter = (Kd / NSPLIT) / BKK;
    issue(0, 0);
    cp_commit();

    float acc[2][4][4] = {};

    for (int i = 0; i < niter; i++) {
        cp_wait<0>();
        __syncthreads();
        if (i + 1 < niter) { issue(i + 1, (i + 1) & 1); cp_commit(); }
        const int s = i & 1;
#pragma unroll
        for (int h = 0; h < 2; h++) {
            const uint32_t sAs = sAu + s * OPB + h * HSB;
            const uint32_t sBs = sBu + s * OPB + h * HSB;
#pragma unroll
            for (int jj = 0; jj < 2; jj++) {
                uint32_t af0[4], af1[4], bf0[4], bf1[4];
                ldsm4(af0, sAs + aOff0 + aqj[jj]);
                ldsm4(af1, sAs + aOff1 + aqj[jj]);
                ldsm4(bf0, sBs + bOff0 + bqj[jj]);
                ldsm4(bf1, sBs + bOff1 + bqj[jj]);
                mma_tf32(acc[0][0], af0, bf0[0], bf0[1]);
                mma_tf32(acc[0][1], af0, bf0[2], bf0[3]);
                mma_tf32(acc[0][2], af0, bf1[0], bf1[1]);
                mma_tf32(acc[0][3], af0, bf1[2], bf1[3]);
                mma_tf32(acc[1][0], af1, bf0[0], bf0[1]);
                mma_tf32(acc[1][1], af1, bf0[2], bf0[3]);
                mma_tf32(acc[1][2], af1, bf1[0], bf1[1]);
                mma_tf32(acc[1][3], af1, bf1[2], bf1[3]);
            }
        }
    }

    // ---- 2-way K-split reduction through smem (aliases pipeline stages) ---
    __syncthreads();
    float* sred = reinterpret_cast<float*>(smem_dyn);   // 4 * 32*33 floats
    const int pi = wm * 2 + wn;
    if (kg == 1) {
#pragma unroll
        for (int mt = 0; mt < 2; mt++)
#pragma unroll
            for (int nt = 0; nt < 4; nt++) {
                int r = mt * 16 + gid, c = nt * 8 + 2 * tig;
                float* base = sred + pi * 1056;
                base[r * 33 + c] = acc[mt][nt][0];
                base[r * 33 + c + 1] = acc[mt][nt][1];
                base[(r + 8) * 33 + c] = acc[mt][nt][2];
                base[(r + 8) * 33 + c + 1] = acc[mt][nt][3];
            }
    }
    __syncthreads();
    if (kg == 0) {
#pragma unroll
        for (int mt = 0; mt < 2; mt++) {
            int r = mt * 16 + gid;
            const float* base = sred + pi * 1056;
            int gr0 = bm0 + wm * 32 + r;
            int gr1 = gr0 + 8;
            float s0 = rsqrt_pos(sumvec[gr0]);
            float s1 = rsqrt_pos(sumvec[gr1]);
#pragma unroll
            for (int nt = 0; nt < 4; nt++) {
                int c = nt * 8 + 2 * tig;
                float v00 = (acc[mt][nt][0] + base[r * 33 + c]) * s0;
                float v01 = (acc[mt][nt][1] + base[r * 33 + c + 1]) * s0;
                float v10 = (acc[mt][nt][2] + base[(r + 8) * 33 + c]) * s1;
                float v11 = (acc[mt][nt][3] + base[(r + 8) * 33 + c + 1]) * s1;
                if (TRANSOUT) {
                    int n0 = bn0 + wn * 32 + c;
                    C[(size_t)n0 * NN + gr0] = __uint_as_float(f2tf32(v00));
                    C[(size_t)(n0 + 1) * NN + gr0] = __uint_as_float(f2tf32(v01));
                    C[(size_t)n0 * NN + gr1] = __uint_as_float(f2tf32(v10));
                    C[(size_t)(n0 + 1) * NN + gr1] = __uint_as_float(f2tf32(v11));
                } else {
                    int col = bn0 + wn * 32 + c;
                    *reinterpret_cast<float2*>(&C[(size_t)gr0 * HIDD + col]) =
                        make_float2(v00, v01);
                    *reinterpret_cast<float2*>(&C[(size_t)gr1 * HIDD + col]) =
                        make_float2(v10, v11);
                }
            }
        }
    }
}

// GEMM1: g_XWt = (dc * (x @ Wg1))^T, tf32-rounded, for gemm2's B operand
__global__ __launch_bounds__(256) void gemm1_kernel() {
    gemm_body<true, 1>(g_Xt, g_Bt1, g_XWt, IN_DIM, g_colsum);
}
// GEMM2: g_AXW[z] = dr * (g_A @ XW) partial over K-quarter z
__global__ __launch_bounds__(256) void gemm2_kernel() {
    gemm_body<false, 4>(g_A, g_XWt, g_AXW[blockIdx.z], NN, g_rowsum);
}

// ---------------- hid = (sum_z AXW_z) @ Wl2 + bl2;  HW = dc * (hid @ Wg2) --
__global__ __launch_bounds__(256) void hid_kernel(const float* __restrict__ Wl2,
                                                  const float* __restrict__ bl2,
                                                  const float* __restrict__ Wg2,
                                                  float* __restrict__ hid_out) {
    __shared__ float sAXW[16][HIDD];
    __shared__ float sHid[16][L2DIM + 1];
    int tid = threadIdx.x;
    int rowbase = blockIdx.x * 16;

#pragma unroll
    for (int t = 0; t < 16; t++) {
        size_t idx = (size_t)rowbase * HIDD + tid + t * 256;
        float v = g_AXW[0][idx] + g_AXW[1][idx] + g_AXW[2][idx] + g_AXW[3][idx];
        int li = tid + t * 256;
        sAXW[li >> 8][li & 255] = v;
    }
    __syncthreads();

    int c = tid & 63;
    int rq = tid >> 6;
    float acc[4];
    float b = bl2[c];
#pragma unroll
    for (int it = 0; it < 4; it++) acc[it] = b;
#pragma unroll 4
    for (int k = 0; k < HIDD; k++) {
        float w = __ldg(&Wl2[k * L2DIM + c]);
#pragma unroll
        for (int it = 0; it < 4; it++)
            acc[it] = fmaf(sAXW[it * 4 + rq][k], w, acc[it]);
    }
#pragma unroll
    for (int it = 0; it < 4; it++) {
        int row = it * 4 + rq;
        hid_out[(size_t)(rowbase + row) * L2DIM + c] = acc[it];
        sHid[row][c] = acc[it];
    }
    __syncthreads();
    if (tid < 64) {
        int r = tid >> 2, cls = tid & 3;
        float s = 0.f;
#pragma unroll
        for (int k = 0; k < L2DIM; k++) s = fmaf(sHid[r][k], Wg2[k * NCLS + cls], s);
        g_HW[(size_t)(rowbase + r) * NCLS + cls] = s * rsqrt_pos(g_colsum[rowbase + r]);
    }
}

// ---------------- out[i] = dr[i] * sum_j A[i,j] * HW[j] --------------------
__global__ __launch_bounds__(256) void out_kernel(float* __restrict__ out) {
    int tid = threadIdx.x;
    __shared__ float4 sHW[NN];
    const float4* hw4 = reinterpret_cast<const float4*>(g_HW);
#pragma unroll
    for (int t = 0; t < NN / 256; t++) sHW[tid + t * 256] = hw4[tid + t * 256];
    __syncthreads();

    __shared__ float red[8][4];
    for (int r = 0; r < 8; r++) {
        int i = blockIdx.x * 8 + r;
        const float* arow = g_A + (size_t)i * NN;
        float ax = 0.f, ay = 0.f, az = 0.f, aw = 0.f;
#pragma unroll
        for (int t = 0; t < NN / 256; t++) {
            int j = tid + t * 256;
            float a = arow[j];
            float4 h = sHW[j];
            ax = fmaf(a, h.x, ax);
            ay = fmaf(a, h.y, ay);
            az = fmaf(a, h.z, az);
            aw = fmaf(a, h.w, aw);
        }
        for (int off = 16; off; off >>= 1) {
            ax += __shfl_down_sync(0xffffffffu, ax, off);
            ay += __shfl_down_sync(0xffffffffu, ay, off);
            az += __shfl_down_sync(0xffffffffu, az, off);
            aw += __shfl_down_sync(0xffffffffu, aw, off);
        }
        if ((tid & 31) == 0) {
            int w = tid >> 5;
            red[w][0] = ax; red[w][1] = ay; red[w][2] = az; red[w][3] = aw;
        }
        __syncthreads();
        if (tid < 4) {
            float s = 0.f;
#pragma unroll
            for (int w = 0; w < 8; w++) s += red[w][tid];
            out[i * NCLS + tid] = rsqrt_pos(g_rowsum[i]) * s;
        }
        __syncthreads();
    }
}

// ---------------- launch --------------------------------------------------
extern "C" void kernel_launch(void* const* d_in, const int* in_sizes, int n_in,
                              void* d_out, int out_size) {
    const float* x    = (const float*)d_in[0];
    const float* adj  = (const float*)d_in[1];
    const float* xdeg = (const float*)d_in[2];
    const float* ydeg = (const float*)d_in[3];
    const float* Wm1  = (const float*)d_in[4];
    const float* bm1  = (const float*)d_in[5];
    const float* Wm2  = (const float*)d_in[6];
    const float* bm2  = (const float*)d_in[7];
    const float* Wg1  = (const float*)d_in[8];
    const float* Wl2  = (const float*)d_in[9];
    const float* bl2  = (const float*)d_in[10];
    const float* Wg2  = (const float*)d_in[11];

    float* out = (float*)d_out;               // [2048, 4]
    float* hid = out + (size_t)NN * NCLS;     // [2048, 64]

    static bool attr_done = false;
    if (!attr_done) {
        cudaFuncSetAttribute(gemm1_kernel,
                             cudaFuncAttributeMaxDynamicSharedMemorySize, GEMM_SMEM);
        cudaFuncSetAttribute(gemm2_kernel,
                             cudaFuncAttributeMaxDynamicSharedMemorySize, GEMM_SMEM);
        attr_done = true;
    }

    edge_kernel<<<NN, 256>>>(adj, xdeg, ydeg, Wm1, bm1, Wm2, bm2);
    prep_kernel<<<896, 256>>>(x, Wg1);
    gemm1_kernel<<<dim3(HIDD / 64, NN / 64, 1), 256, GEMM_SMEM>>>();
    gemm2_kernel<<<dim3(HIDD / 64, NN / 64, 4), 256, GEMM_SMEM>>>();
    hid_kernel<<<NN / 16, 256>>>(Wl2, bl2, Wg2, hid);
    out_kernel<<<NN / 8, 256>>>(out);
}